// round 2
// baseline (speedup 1.0000x reference)
#include <cuda_runtime.h>
#include <math.h>

#define D_MODEL 1024
#define D_FF    2048
#define NE      8
#define TMAX    2048

// -------- device scratch (static allocation; no cudaMalloc allowed) --------
__device__ int    g_count[NE];
__device__ double g_probsum[NE];
__device__ int    g_tok[NE * TMAX];
__device__ float  g_wt[NE * TMAX];
__device__ float  g_H[(size_t)NE * TMAX * D_FF];   // 134 MB slot-major H

// ---------------------------------------------------------------------------
__global__ void zero_kernel() {
    int i = threadIdx.x;
    if (i < NE) { g_count[i] = 0; g_probsum[i] = 0.0; }
}

// One block per token: 8 warps compute the 8 logits, thread 0 does softmax,
// top-2 selection, list append, prob-sum accumulation (double).
__global__ void router_kernel(const float* __restrict__ x,
                              const float* __restrict__ gw,
                              const float* __restrict__ gb) {
    int t    = blockIdx.x;
    int warp = threadIdx.x >> 5;
    int lane = threadIdx.x & 31;
    __shared__ float logits[NE];

    const float* xr = x + (size_t)t * D_MODEL;
    const float* w  = gw + warp * D_MODEL;
    float s = 0.f;
    for (int i = lane; i < D_MODEL; i += 32) s += xr[i] * w[i];
    #pragma unroll
    for (int o = 16; o > 0; o >>= 1) s += __shfl_down_sync(0xffffffff, s, o);
    if (lane == 0) logits[warp] = s + gb[warp];
    __syncthreads();

    if (threadIdx.x == 0) {
        float p[NE];
        float mx = -1e30f;
        #pragma unroll
        for (int e = 0; e < NE; e++) mx = fmaxf(mx, logits[e]);
        float sum = 0.f;
        #pragma unroll
        for (int e = 0; e < NE; e++) { p[e] = expf(logits[e] - mx); sum += p[e]; }
        float inv = 1.f / sum;
        #pragma unroll
        for (int e = 0; e < NE; e++) {
            p[e] *= inv;
            atomicAdd(&g_probsum[e], (double)p[e]);
        }
        // top-2 (strict >, so ties pick lowest index, matching jax top_k)
        int i0 = 0;
        #pragma unroll
        for (int e = 1; e < NE; e++) if (p[e] > p[i0]) i0 = e;
        int i1 = -1;
        #pragma unroll
        for (int e = 0; e < NE; e++) {
            if (e == i0) continue;
            if (i1 < 0 || p[e] > p[i1]) i1 = e;
        }
        float v0 = p[i0], v1 = p[i1];
        float inv2 = 1.f / (v0 + v1);
        int s0 = atomicAdd(&g_count[i0], 1);
        g_tok[i0 * TMAX + s0] = t;  g_wt[i0 * TMAX + s0] = v0 * inv2;
        int s1 = atomicAdd(&g_count[i1], 1);
        g_tok[i1 * TMAX + s1] = t;  g_wt[i1 * TMAX + s1] = v1 * inv2;
    }
}

__global__ void loss_kernel(float* __restrict__ out_loss, int T) {
    if (threadIdx.x == 0) {
        const double ideal = 1.0 / NE;
        double l = 0.0;
        #pragma unroll
        for (int e = 0; e < NE; e++) {
            double mp = g_probsum[e] / (double)T + 1e-9;
            l += ideal * (log(ideal) - log(mp));
        }
        *out_loss = (float)l;
    }
}

// ---------------------------------------------------------------------------
// Fused gate+up GEMM (+bias, SiLU, elementwise mul) -> H scratch.
// Tile 64x64, K-step 16, 256 threads, 4x4 microtile, shared A between the two
// B operands. Rows are gathered through the per-expert token list.
__global__ __launch_bounds__(256)
void gemm_gu_kernel(const float* __restrict__ x,
                    const float* __restrict__ Wg, const float* __restrict__ bg,
                    const float* __restrict__ Wu, const float* __restrict__ bu) {
    int e = blockIdx.z;
    int n = g_count[e];
    int rowbase = blockIdx.y * 64;
    if (rowbase >= n) return;
    int colbase = blockIdx.x * 64;

    __shared__ float As[16][65];
    __shared__ float Bg[16][64];
    __shared__ float Bu[16][64];
    __shared__ int   toks[64];

    int tid = threadIdx.x;
    if (tid < 64) {
        int r = rowbase + tid;
        toks[tid] = (r < n) ? g_tok[e * TMAX + r] : g_tok[e * TMAX];
    }
    __syncthreads();

    int ty = tid >> 4, tx = tid & 15;
    float ag[4][4] = {}, au[4][4] = {};

    const float* wgp = Wg + (size_t)e * D_MODEL * D_FF;
    const float* wup = Wu + (size_t)e * D_MODEL * D_FF;

    for (int k0 = 0; k0 < D_MODEL; k0 += 16) {
        #pragma unroll
        for (int pass = 0; pass < 4; pass++) {
            int m = (tid >> 4) + pass * 16;
            int k = tid & 15;
            As[k][m] = x[(size_t)toks[m] * D_MODEL + k0 + k];
        }
        #pragma unroll
        for (int pass = 0; pass < 4; pass++) {
            int kk = (tid >> 6) + pass * 4;
            int nn = tid & 63;
            Bg[kk][nn] = wgp[(size_t)(k0 + kk) * D_FF + colbase + nn];
            Bu[kk][nn] = wup[(size_t)(k0 + kk) * D_FF + colbase + nn];
        }
        __syncthreads();
        #pragma unroll
        for (int kk = 0; kk < 16; kk++) {
            float a[4], bgv[4], buv[4];
            #pragma unroll
            for (int i = 0; i < 4; i++) a[i] = As[kk][ty + 16 * i];
            #pragma unroll
            for (int j = 0; j < 4; j++) { bgv[j] = Bg[kk][tx + 16 * j]; buv[j] = Bu[kk][tx + 16 * j]; }
            #pragma unroll
            for (int i = 0; i < 4; i++)
                #pragma unroll
                for (int j = 0; j < 4; j++) {
                    ag[i][j] += a[i] * bgv[j];
                    au[i][j] += a[i] * buv[j];
                }
        }
        __syncthreads();
    }

    #pragma unroll
    for (int i = 0; i < 4; i++) {
        int m = ty + 16 * i;
        int r = rowbase + m;
        if (r >= n) continue;
        float* hrow = g_H + ((size_t)e * TMAX + r) * D_FF + colbase;
        #pragma unroll
        for (int j = 0; j < 4; j++) {
            int nn = tx + 16 * j;
            float g = ag[i][j] + bg[e * D_FF + colbase + nn];
            float u = au[i][j] + bu[e * D_FF + colbase + nn];
            float h = (g / (1.f + expf(-g))) * u;   // silu(g)*u
            hrow[nn] = h;
        }
    }
}

// Down GEMM + bias, scaled by combine weight, atomic scatter-add into out.
__global__ __launch_bounds__(256)
void gemm_down_kernel(const float* __restrict__ Wd,
                      const float* __restrict__ bd,
                      float* __restrict__ out) {
    int e = blockIdx.z;
    int n = g_count[e];
    int rowbase = blockIdx.y * 64;
    if (rowbase >= n) return;
    int colbase = blockIdx.x * 64;

    __shared__ float As[16][65];
    __shared__ float Bs[16][64];

    int tid = threadIdx.x;
    int ty = tid >> 4, tx = tid & 15;
    float acc[4][4] = {};

    const float* wdp   = Wd + (size_t)e * D_FF * D_MODEL;
    const float* hbase = g_H + (size_t)e * TMAX * D_FF;

    for (int k0 = 0; k0 < D_FF; k0 += 16) {
        #pragma unroll
        for (int pass = 0; pass < 4; pass++) {
            int m = (tid >> 4) + pass * 16;
            int k = tid & 15;
            int r = rowbase + m;
            As[k][m] = (r < n) ? hbase[(size_t)r * D_FF + k0 + k] : 0.f;
        }
        #pragma unroll
        for (int pass = 0; pass < 4; pass++) {
            int kk = (tid >> 6) + pass * 4;
            int nn = tid & 63;
            Bs[kk][nn] = wdp[(size_t)(k0 + kk) * D_MODEL + colbase + nn];
        }
        __syncthreads();
        #pragma unroll
        for (int kk = 0; kk < 16; kk++) {
            float a[4], b[4];
            #pragma unroll
            for (int i = 0; i < 4; i++) a[i] = As[kk][ty + 16 * i];
            #pragma unroll
            for (int j = 0; j < 4; j++) b[j] = Bs[kk][tx + 16 * j];
            #pragma unroll
            for (int i = 0; i < 4; i++)
                #pragma unroll
                for (int j = 0; j < 4; j++) acc[i][j] += a[i] * b[j];
        }
        __syncthreads();
    }

    #pragma unroll
    for (int i = 0; i < 4; i++) {
        int m = ty + 16 * i;
        int r = rowbase + m;
        if (r >= n) continue;
        int   t = g_tok[e * TMAX + r];
        float w = g_wt[e * TMAX + r];
        #pragma unroll
        for (int j = 0; j < 4; j++) {
            int nn = tx + 16 * j;
            float y = acc[i][j] + bd[e * D_MODEL + colbase + nn];
            atomicAdd(&out[(size_t)t * D_MODEL + colbase + nn], w * y);
        }
    }
}

// ---------------------------------------------------------------------------
extern "C" void kernel_launch(void* const* d_in, const int* in_sizes, int n_in,
                              void* d_out, int out_size) {
    const float* x  = (const float*)d_in[0];
    const float* gw = (const float*)d_in[1];
    const float* gb = (const float*)d_in[2];
    const float* Wg = (const float*)d_in[3];
    const float* bg = (const float*)d_in[4];
    const float* Wu = (const float*)d_in[5];
    const float* bu = (const float*)d_in[6];
    const float* Wd = (const float*)d_in[7];
    const float* bd = (const float*)d_in[8];
    float* out = (float*)d_out;

    int T = in_sizes[0] / D_MODEL;   // 2048

    cudaMemsetAsync(out, 0, (size_t)T * D_MODEL * sizeof(float));
    zero_kernel<<<1, 32>>>();
    router_kernel<<<T, 256>>>(x, gw, gb);
    if (out_size > T * D_MODEL) {
        loss_kernel<<<1, 32>>>(out + (size_t)T * D_MODEL, T);
    }
    dim3 g1(D_FF / 64, (T + 63) / 64, NE);
    gemm_gu_kernel<<<g1, 256>>>(x, Wg, bg, Wu, bu);
    dim3 g2(D_MODEL / 64, (T + 63) / 64, NE);
    gemm_down_kernel<<<g2, 256>>>(Wd, bd, out);
}

// round 3
// speedup vs baseline: 1.2324x; 1.2324x over previous
#include <cuda_runtime.h>
#include <math.h>

#define D_MODEL 1024
#define D_FF    2048
#define NE      8
#define TMAX    2048
#define BM 128
#define BN 128
#define BK 16

// -------- device scratch (static allocation; no cudaMalloc allowed) --------
__device__ int    g_count[NE];
__device__ double g_probsum[NE];
__device__ int    g_tok[NE * TMAX];
__device__ float  g_wt[NE * TMAX];
__device__ float  g_G[(size_t)NE * TMAX * D_FF];   // gate pre-activation (+bias)
__device__ float  g_U[(size_t)NE * TMAX * D_FF];   // up   pre-activation (+bias)

// ---------------------------------------------------------------------------
__global__ void zero_kernel() {
    int i = threadIdx.x;
    if (i < NE) { g_count[i] = 0; g_probsum[i] = 0.0; }
}

// One block per token: 8 warps compute the 8 logits, thread 0 does softmax,
// top-2 selection, list append, prob-sum accumulation (double).
__global__ void router_kernel(const float* __restrict__ x,
                              const float* __restrict__ gw,
                              const float* __restrict__ gb) {
    int t    = blockIdx.x;
    int warp = threadIdx.x >> 5;
    int lane = threadIdx.x & 31;
    __shared__ float logits[NE];

    const float* xr = x + (size_t)t * D_MODEL;
    const float* w  = gw + warp * D_MODEL;
    float s = 0.f;
    for (int i = lane; i < D_MODEL; i += 32) s += xr[i] * w[i];
    #pragma unroll
    for (int o = 16; o > 0; o >>= 1) s += __shfl_down_sync(0xffffffff, s, o);
    if (lane == 0) logits[warp] = s + gb[warp];
    __syncthreads();

    if (threadIdx.x == 0) {
        float p[NE];
        float mx = -1e30f;
        #pragma unroll
        for (int e = 0; e < NE; e++) mx = fmaxf(mx, logits[e]);
        float sum = 0.f;
        #pragma unroll
        for (int e = 0; e < NE; e++) { p[e] = expf(logits[e] - mx); sum += p[e]; }
        float inv = 1.f / sum;
        #pragma unroll
        for (int e = 0; e < NE; e++) {
            p[e] *= inv;
            atomicAdd(&g_probsum[e], (double)p[e]);
        }
        int i0 = 0;
        #pragma unroll
        for (int e = 1; e < NE; e++) if (p[e] > p[i0]) i0 = e;
        int i1 = -1;
        #pragma unroll
        for (int e = 0; e < NE; e++) {
            if (e == i0) continue;
            if (i1 < 0 || p[e] > p[i1]) i1 = e;
        }
        float v0 = p[i0], v1 = p[i1];
        float inv2 = 1.f / (v0 + v1);
        int s0 = atomicAdd(&g_count[i0], 1);
        g_tok[i0 * TMAX + s0] = t;  g_wt[i0 * TMAX + s0] = v0 * inv2;
        int s1 = atomicAdd(&g_count[i1], 1);
        g_tok[i1 * TMAX + s1] = t;  g_wt[i1 * TMAX + s1] = v1 * inv2;
    }
}

__global__ void loss_kernel(float* __restrict__ out_loss, int T) {
    if (threadIdx.x == 0) {
        const double ideal = 1.0 / NE;
        double l = 0.0;
        #pragma unroll
        for (int e = 0; e < NE; e++) {
            double mp = g_probsum[e] / (double)T + 1e-9;
            l += ideal * (log(ideal) - log(mp));
        }
        *out_loss = (float)l;
    }
}

// ---------------------------------------------------------------------------
// GEMM 1: G/U = gather(x) @ {Wg|Wu} + {bg|bu}.
// 128x128x16 tile, 256 threads, 8x8 microtile, float4 shared loads.
// blockIdx.x < 16 -> gate (Wg->G), >= 16 -> up (Wu->U).
__global__ __launch_bounds__(256, 2)
void gemm_gu_kernel(const float* __restrict__ x,
                    const float* __restrict__ Wg, const float* __restrict__ bg,
                    const float* __restrict__ Wu, const float* __restrict__ bu) {
    int e = blockIdx.z;
    int n = g_count[e];
    int rowbase = blockIdx.y * BM;
    if (rowbase >= n) return;

    bool isU   = blockIdx.x >= (D_FF / BN);
    int colbase = (blockIdx.x & (D_FF / BN - 1)) * BN;

    const float* W    = (isU ? Wu : Wg) + (size_t)e * D_MODEL * D_FF;
    const float* bias = (isU ? bu : bg) + e * D_FF + colbase;
    float*       dst  = (isU ? g_U : g_G) + (size_t)e * TMAX * D_FF;

    __shared__ float As[BK][136];
    __shared__ float Bs[BK][BN];
    __shared__ int   toks[BM];

    int tid = threadIdx.x;
    if (tid < BM) {
        int r = rowbase + tid;
        toks[tid] = g_tok[e * TMAX + (r < n ? r : n - 1)];
    }
    __syncthreads();

    int ty = tid >> 4, tx = tid & 15;
    float acc[8][8] = {};

    int arow = tid >> 1;
    int akq  = (tid & 1) * 8;
    const float* aptr = x + (size_t)toks[arow] * D_MODEL + akq;

    int brow = tid >> 5;                 // 0..7
    int bcol = (tid & 31) * 4;
    const float* bptr = W + (size_t)brow * D_FF + colbase + bcol;

    for (int k0 = 0; k0 < D_MODEL; k0 += BK) {
        float4 a0 = *(const float4*)(aptr + k0);
        float4 a1 = *(const float4*)(aptr + k0 + 4);
        float4 b0 = *(const float4*)(bptr + (size_t)k0 * D_FF);
        float4 b1 = *(const float4*)(bptr + (size_t)(k0 + 8) * D_FF);

        As[akq + 0][arow] = a0.x; As[akq + 1][arow] = a0.y;
        As[akq + 2][arow] = a0.z; As[akq + 3][arow] = a0.w;
        As[akq + 4][arow] = a1.x; As[akq + 5][arow] = a1.y;
        As[akq + 6][arow] = a1.z; As[akq + 7][arow] = a1.w;
        *(float4*)&Bs[brow][bcol]     = b0;
        *(float4*)&Bs[brow + 8][bcol] = b1;
        __syncthreads();

        #pragma unroll
        for (int kk = 0; kk < BK; kk++) {
            float4 av0 = *(const float4*)&As[kk][ty * 8];
            float4 av1 = *(const float4*)&As[kk][ty * 8 + 4];
            float4 bv0 = *(const float4*)&Bs[kk][tx * 8];
            float4 bv1 = *(const float4*)&Bs[kk][tx * 8 + 4];
            float av[8] = {av0.x, av0.y, av0.z, av0.w, av1.x, av1.y, av1.z, av1.w};
            float bv[8] = {bv0.x, bv0.y, bv0.z, bv0.w, bv1.x, bv1.y, bv1.z, bv1.w};
            #pragma unroll
            for (int i = 0; i < 8; i++)
                #pragma unroll
                for (int j = 0; j < 8; j++) acc[i][j] += av[i] * bv[j];
        }
        __syncthreads();
    }

    #pragma unroll
    for (int i = 0; i < 8; i++) {
        int r = rowbase + ty * 8 + i;
        if (r >= n) continue;
        float* drow = dst + (size_t)r * D_FF + colbase;
        #pragma unroll
        for (int j = 0; j < 8; j++) {
            int c = tx * 8 + j;
            drow[c] = acc[i][j] + bias[c];
        }
    }
}

// ---------------------------------------------------------------------------
// GEMM 2: out += cw * ( (silu(G)*U) @ Wd + bd ), A computed on the fly.
__global__ __launch_bounds__(256, 2)
void gemm_down_kernel(const float* __restrict__ Wd,
                      const float* __restrict__ bd,
                      float* __restrict__ out) {
    int e = blockIdx.z;
    int n = g_count[e];
    int rowbase = blockIdx.y * BM;
    if (rowbase >= n) return;
    int colbase = blockIdx.x * BN;

    const float* W     = Wd + (size_t)e * D_FF * D_MODEL;
    const float* gbase = g_G + (size_t)e * TMAX * D_FF;
    const float* ubase = g_U + (size_t)e * TMAX * D_FF;

    __shared__ float As[BK][136];
    __shared__ float Bs[BK][BN];

    int tid = threadIdx.x;
    int ty = tid >> 4, tx = tid & 15;
    float acc[8][8] = {};

    int arow = tid >> 1;
    int akq  = (tid & 1) * 8;
    int r_a  = rowbase + arow;
    bool avalid = (r_a < n);
    size_t aoff = (size_t)(avalid ? r_a : 0) * D_FF + akq;

    int brow = tid >> 5;
    int bcol = (tid & 31) * 4;
    const float* bptr = W + (size_t)brow * D_MODEL + colbase + bcol;

    for (int k0 = 0; k0 < D_FF; k0 += BK) {
        float4 gv0 = *(const float4*)(gbase + aoff + k0);
        float4 gv1 = *(const float4*)(gbase + aoff + k0 + 4);
        float4 uv0 = *(const float4*)(ubase + aoff + k0);
        float4 uv1 = *(const float4*)(ubase + aoff + k0 + 4);
        float4 b0  = *(const float4*)(bptr + (size_t)k0 * D_MODEL);
        float4 b1  = *(const float4*)(bptr + (size_t)(k0 + 8) * D_MODEL);

        float gs[8] = {gv0.x, gv0.y, gv0.z, gv0.w, gv1.x, gv1.y, gv1.z, gv1.w};
        float us[8] = {uv0.x, uv0.y, uv0.z, uv0.w, uv1.x, uv1.y, uv1.z, uv1.w};
        #pragma unroll
        for (int i = 0; i < 8; i++) {
            float g = gs[i];
            float h = avalid ? (g / (1.f + __expf(-g))) * us[i] : 0.f;
            As[akq + i][arow] = h;
        }
        *(float4*)&Bs[brow][bcol]     = b0;
        *(float4*)&Bs[brow + 8][bcol] = b1;
        __syncthreads();

        #pragma unroll
        for (int kk = 0; kk < BK; kk++) {
            float4 av0 = *(const float4*)&As[kk][ty * 8];
            float4 av1 = *(const float4*)&As[kk][ty * 8 + 4];
            float4 bv0 = *(const float4*)&Bs[kk][tx * 8];
            float4 bv1 = *(const float4*)&Bs[kk][tx * 8 + 4];
            float av[8] = {av0.x, av0.y, av0.z, av0.w, av1.x, av1.y, av1.z, av1.w};
            float bv[8] = {bv0.x, bv0.y, bv0.z, bv0.w, bv1.x, bv1.y, bv1.z, bv1.w};
            #pragma unroll
            for (int i = 0; i < 8; i++)
                #pragma unroll
                for (int j = 0; j < 8; j++) acc[i][j] += av[i] * bv[j];
        }
        __syncthreads();
    }

    #pragma unroll
    for (int i = 0; i < 8; i++) {
        int r = rowbase + ty * 8 + i;
        if (r >= n) continue;
        int   t = g_tok[e * TMAX + r];
        float w = g_wt[e * TMAX + r];
        #pragma unroll
        for (int j = 0; j < 8; j++) {
            int c = colbase + tx * 8 + j;
            float y = acc[i][j] + bd[e * D_MODEL + c];
            atomicAdd(&out[(size_t)t * D_MODEL + c], w * y);
        }
    }
}

// ---------------------------------------------------------------------------
extern "C" void kernel_launch(void* const* d_in, const int* in_sizes, int n_in,
                              void* d_out, int out_size) {
    const float* x  = (const float*)d_in[0];
    const float* gw = (const float*)d_in[1];
    const float* gb = (const float*)d_in[2];
    const float* Wg = (const float*)d_in[3];
    const float* bg = (const float*)d_in[4];
    const float* Wu = (const float*)d_in[5];
    const float* bu = (const float*)d_in[6];
    const float* Wd = (const float*)d_in[7];
    const float* bd = (const float*)d_in[8];
    float* out = (float*)d_out;

    int T = in_sizes[0] / D_MODEL;   // 2048

    cudaMemsetAsync(out, 0, (size_t)T * D_MODEL * sizeof(float));
    zero_kernel<<<1, 32>>>();
    router_kernel<<<T, 256>>>(x, gw, gb);
    if (out_size > T * D_MODEL) {
        loss_kernel<<<1, 32>>>(out + (size_t)T * D_MODEL, T);
    }
    dim3 g1(2 * D_FF / BN, (T + BM - 1) / BM, NE);       // 32 x 16 x 8
    gemm_gu_kernel<<<g1, 256>>>(x, Wg, bg, Wu, bu);
    dim3 g2(D_MODEL / BN, (T + BM - 1) / BM, NE);        // 8 x 16 x 8
    gemm_down_kernel<<<g2, 256>>>(Wd, bd, out);
}

// round 5
// speedup vs baseline: 1.7792x; 1.4437x over previous
#include <cuda_runtime.h>
#include <cuda_fp16.h>
#include <math.h>
#include <stdint.h>

#define D_MODEL 1024
#define D_FF    2048
#define NE      8
#define TMAX    2048

#define BK 32
#define STRA 80                      // A smem row stride bytes (128 rows)
#define STRB 272                     // B smem row stride bytes (32 rows)
#define A_SZ (128 * STRA)            // 10240
#define B_SZ (32 * STRB)             // 8704
#define STAGE (2 * A_SZ + 2 * B_SZ)  // 37888 (Ah|Al|Bh|Bl)
#define SMEM_DYN (2 * STAGE)         // 75776

// -------- device scratch (static; no cudaMalloc allowed) --------
__device__ int    g_count[NE];
__device__ double g_probsum[NE];
__device__ int    g_tok[NE * TMAX];
__device__ float  g_wt[NE * TMAX];
__device__ float  g_G[(size_t)NE * TMAX * D_FF];
__device__ float  g_U[(size_t)NE * TMAX * D_FF];

// ---------------- helpers ----------------
__device__ __forceinline__ uint32_t smem_u32(const void* p) {
    uint32_t a;
    asm("{ .reg .u64 t; cvta.to.shared.u64 t, %1; cvt.u32.u64 %0, t; }" : "=r"(a) : "l"(p));
    return a;
}
__device__ __forceinline__ void split2(float f0, float f1, uint32_t& hi, uint32_t& lo) {
    __half2 h = __floats2half2_rn(f0, f1);
    float2 hf = __half22float2(h);
    __half2 l = __floats2half2_rn(f0 - hf.x, f1 - hf.y);
    hi = *reinterpret_cast<uint32_t*>(&h);
    lo = *reinterpret_cast<uint32_t*>(&l);
}
__device__ __forceinline__ void ldsm_x4(uint32_t* r, uint32_t addr) {
    asm volatile("ldmatrix.sync.aligned.m8n8.x4.shared.b16 {%0,%1,%2,%3}, [%4];"
                 : "=r"(r[0]), "=r"(r[1]), "=r"(r[2]), "=r"(r[3]) : "r"(addr));
}
__device__ __forceinline__ void ldsm_x4t(uint32_t* r, uint32_t addr) {
    asm volatile("ldmatrix.sync.aligned.m8n8.x4.trans.shared.b16 {%0,%1,%2,%3}, [%4];"
                 : "=r"(r[0]), "=r"(r[1]), "=r"(r[2]), "=r"(r[3]) : "r"(addr));
}
__device__ __forceinline__ void mma16816(float* c, const uint32_t* a, const uint32_t* b) {
    asm volatile("mma.sync.aligned.m16n8k16.row.col.f32.f16.f16.f32 "
                 "{%0,%1,%2,%3}, {%4,%5,%6,%7}, {%8,%9}, {%0,%1,%2,%3};"
                 : "+f"(c[0]), "+f"(c[1]), "+f"(c[2]), "+f"(c[3])
                 : "r"(a[0]), "r"(a[1]), "r"(a[2]), "r"(a[3]), "r"(b[0]), "r"(b[1]));
}

// ---------------------------------------------------------------------------
__global__ void zero_kernel() {
    int i = threadIdx.x;
    if (i < NE) { g_count[i] = 0; g_probsum[i] = 0.0; }
}

__global__ void router_kernel(const float* __restrict__ x,
                              const float* __restrict__ gw,
                              const float* __restrict__ gb) {
    int t    = blockIdx.x;
    int warp = threadIdx.x >> 5;
    int lane = threadIdx.x & 31;
    __shared__ float logits[NE];

    const float* xr = x + (size_t)t * D_MODEL;
    const float* w  = gw + warp * D_MODEL;
    float s = 0.f;
    for (int i = lane; i < D_MODEL; i += 32) s += xr[i] * w[i];
    #pragma unroll
    for (int o = 16; o > 0; o >>= 1) s += __shfl_down_sync(0xffffffff, s, o);
    if (lane == 0) logits[warp] = s + gb[warp];
    __syncthreads();

    if (threadIdx.x == 0) {
        float p[NE];
        float mx = -1e30f;
        #pragma unroll
        for (int e = 0; e < NE; e++) mx = fmaxf(mx, logits[e]);
        float sum = 0.f;
        #pragma unroll
        for (int e = 0; e < NE; e++) { p[e] = expf(logits[e] - mx); sum += p[e]; }
        float inv = 1.f / sum;
        #pragma unroll
        for (int e = 0; e < NE; e++) {
            p[e] *= inv;
            atomicAdd(&g_probsum[e], (double)p[e]);
        }
        int i0 = 0;
        #pragma unroll
        for (int e = 1; e < NE; e++) if (p[e] > p[i0]) i0 = e;
        int i1 = -1;
        #pragma unroll
        for (int e = 0; e < NE; e++) {
            if (e == i0) continue;
            if (i1 < 0 || p[e] > p[i1]) i1 = e;
        }
        float v0 = p[i0], v1 = p[i1];
        float inv2 = 1.f / (v0 + v1);
        int s0 = atomicAdd(&g_count[i0], 1);
        g_tok[i0 * TMAX + s0] = t;  g_wt[i0 * TMAX + s0] = v0 * inv2;
        int s1 = atomicAdd(&g_count[i1], 1);
        g_tok[i1 * TMAX + s1] = t;  g_wt[i1 * TMAX + s1] = v1 * inv2;
    }
}

__global__ void loss_kernel(float* __restrict__ out_loss, int T) {
    if (threadIdx.x == 0) {
        const double ideal = 1.0 / NE;
        double l = 0.0;
        #pragma unroll
        for (int e = 0; e < NE; e++) {
            double mp = g_probsum[e] / (double)T + 1e-9;
            l += ideal * (log(ideal) - log(mp));
        }
        *out_loss = (float)l;
    }
}

// ---------------------------------------------------------------------------
// GU: C = gather(x) @ W + bias -> G or U (fp32 scratch).
// 128x128x32 tile, mma.m16n8k16.f16, 3-term split emulation.
__global__ __launch_bounds__(256)
void gu_kernel(const float* __restrict__ x,
               const float* __restrict__ Wg, const float* __restrict__ bg,
               const float* __restrict__ Wu, const float* __restrict__ bu) {
    int e = blockIdx.z;
    int n = g_count[e];
    int rowbase = blockIdx.y * 128;
    if (rowbase >= n) return;
    bool isU = blockIdx.x >= (D_FF / 128);
    int colbase = (blockIdx.x & (D_FF / 128 - 1)) * 128;

    const float* W    = (isU ? Wu : Wg) + (size_t)e * D_MODEL * D_FF;
    const float* bias = (isU ? bu : bg) + e * D_FF + colbase;
    float*       dst  = (isU ? g_U : g_G) + (size_t)e * TMAX * D_FF;

    extern __shared__ char sm[];
    __shared__ int toks[128];
    uint32_t sbase = smem_u32(sm);

    int tid = threadIdx.x, lane = tid & 31, wid = tid >> 5;
    int wm = wid >> 2, wn = wid & 3;

    if (tid < 128) {
        int r = rowbase + tid;
        toks[tid] = g_tok[e * TMAX + (r < n ? r : n - 1)];
    }
    __syncthreads();

    float4 aReg[4], bReg[4];
    auto ldg = [&](int k0) {
        #pragma unroll
        for (int it = 0; it < 4; it++) {
            int idx = tid + it * 256;
            int arow = idx >> 3, aseg = idx & 7;
            aReg[it] = *(const float4*)(x + (size_t)toks[arow] * D_MODEL + k0 + aseg * 4);
            int brow = idx >> 5, bseg = idx & 31;
            bReg[it] = *(const float4*)(W + (size_t)(k0 + brow) * D_FF + colbase + bseg * 4);
        }
    };
    auto sts = [&](int buf) {
        char* st = sm + buf * STAGE;
        #pragma unroll
        for (int it = 0; it < 4; it++) {
            int idx = tid + it * 256;
            int arow = idx >> 3, aseg = idx & 7;
            uint32_t h0, h1, l0, l1;
            split2(aReg[it].x, aReg[it].y, h0, l0);
            split2(aReg[it].z, aReg[it].w, h1, l1);
            *(uint2*)(st + arow * STRA + aseg * 8)        = make_uint2(h0, h1);
            *(uint2*)(st + A_SZ + arow * STRA + aseg * 8) = make_uint2(l0, l1);
            int brow = idx >> 5, bseg = idx & 31;
            split2(bReg[it].x, bReg[it].y, h0, l0);
            split2(bReg[it].z, bReg[it].w, h1, l1);
            *(uint2*)(st + 2 * A_SZ + brow * STRB + bseg * 8)        = make_uint2(h0, h1);
            *(uint2*)(st + 2 * A_SZ + B_SZ + brow * STRB + bseg * 8) = make_uint2(l0, l1);
        }
    };

    float acc[4][4][4] = {};
    int ar = lane & 15, ac = lane >> 4;          // A ldsm addr parts
    int kr = lane & 7,  sel = lane >> 3;         // B ldsm addr parts

    auto compute = [&](int buf) {
        uint32_t Ah = sbase + buf * STAGE;
        uint32_t Al = Ah + A_SZ;
        uint32_t Bh = Ah + 2 * A_SZ;
        uint32_t Bl = Bh + B_SZ;
        #pragma unroll
        for (int ks = 0; ks < 2; ks++) {
            uint32_t ah[4][4], al[4][4], bh[8], bl[8];
            #pragma unroll
            for (int mt = 0; mt < 4; mt++) {
                uint32_t off = (uint32_t)((wm * 64 + mt * 16 + ar) * STRA + (ks * 16 + ac * 8) * 2);
                ldsm_x4(ah[mt], Ah + off);
                ldsm_x4(al[mt], Al + off);
            }
            #pragma unroll
            for (int nt2 = 0; nt2 < 2; nt2++) {
                int rowk = ks * 16 + (sel & 1) * 8 + kr;
                int coln = wn * 32 + nt2 * 16 + (sel >> 1) * 8;
                uint32_t off = (uint32_t)(rowk * STRB + coln * 2);
                ldsm_x4t(&bh[nt2 * 4], Bh + off);
                ldsm_x4t(&bl[nt2 * 4], Bl + off);
            }
            #pragma unroll
            for (int mt = 0; mt < 4; mt++)
                #pragma unroll
                for (int nt = 0; nt < 4; nt++) {
                    const uint32_t* bhp = &bh[(nt >> 1) * 4 + (nt & 1) * 2];
                    const uint32_t* blp = &bl[(nt >> 1) * 4 + (nt & 1) * 2];
                    mma16816(acc[mt][nt], ah[mt], bhp);
                    mma16816(acc[mt][nt], ah[mt], blp);
                    mma16816(acc[mt][nt], al[mt], bhp);
                }
        }
    };

    const int NIT = D_MODEL / BK;   // 32
    ldg(0); sts(0);
    for (int i = 0; i < NIT; i++) {
        __syncthreads();
        if (i + 1 < NIT) ldg((i + 1) * BK);
        compute(i & 1);
        if (i + 1 < NIT) sts((i + 1) & 1);
    }

    // epilogue: acc + bias -> dst (fp32)
    #pragma unroll
    for (int mt = 0; mt < 4; mt++) {
        int r0 = rowbase + wm * 64 + mt * 16 + (lane >> 2);
        #pragma unroll
        for (int nt = 0; nt < 4; nt++) {
            int c = wn * 32 + nt * 8 + (lane & 3) * 2;
            float b0 = bias[c], b1 = bias[c + 1];
            if (r0 < n) {
                float* p = dst + (size_t)r0 * D_FF + colbase + c;
                p[0] = acc[mt][nt][0] + b0;
                p[1] = acc[mt][nt][1] + b1;
            }
            if (r0 + 8 < n) {
                float* p = dst + (size_t)(r0 + 8) * D_FF + colbase + c;
                p[0] = acc[mt][nt][2] + b0;
                p[1] = acc[mt][nt][3] + b1;
            }
        }
    }
}

// ---------------------------------------------------------------------------
// Down: out[t] += w * ( (silu(G)*U) @ Wd + bd ), h computed during staging.
__global__ __launch_bounds__(256)
void dn_kernel(const float* __restrict__ Wd, const float* __restrict__ bd,
               float* __restrict__ out) {
    int e = blockIdx.z;
    int n = g_count[e];
    int rowbase = blockIdx.y * 128;
    if (rowbase >= n) return;
    int colbase = blockIdx.x * 128;

    const float* W     = Wd + (size_t)e * D_FF * D_MODEL;
    const float* Gp    = g_G + (size_t)e * TMAX * D_FF;
    const float* Up    = g_U + (size_t)e * TMAX * D_FF;

    extern __shared__ char sm[];
    uint32_t sbase = smem_u32(sm);

    int tid = threadIdx.x, lane = tid & 31, wid = tid >> 5;
    int wm = wid >> 2, wn = wid & 3;

    float4 hReg[4], bReg[4];
    auto ldg = [&](int k0) {
        #pragma unroll
        for (int it = 0; it < 4; it++) {
            int idx = tid + it * 256;
            int arow = idx >> 3, aseg = idx & 7;
            int r = rowbase + arow; if (r >= n) r = n - 1;
            size_t o = (size_t)r * D_FF + k0 + aseg * 4;
            float4 g = *(const float4*)(Gp + o);
            float4 u = *(const float4*)(Up + o);
            hReg[it].x = g.x / (1.f + __expf(-g.x)) * u.x;
            hReg[it].y = g.y / (1.f + __expf(-g.y)) * u.y;
            hReg[it].z = g.z / (1.f + __expf(-g.z)) * u.z;
            hReg[it].w = g.w / (1.f + __expf(-g.w)) * u.w;
            int brow = idx >> 5, bseg = idx & 31;
            bReg[it] = *(const float4*)(W + (size_t)(k0 + brow) * D_MODEL + colbase + bseg * 4);
        }
    };
    auto sts = [&](int buf) {
        char* st = sm + buf * STAGE;
        #pragma unroll
        for (int it = 0; it < 4; it++) {
            int idx = tid + it * 256;
            int arow = idx >> 3, aseg = idx & 7;
            uint32_t h0, h1, l0, l1;
            split2(hReg[it].x, hReg[it].y, h0, l0);
            split2(hReg[it].z, hReg[it].w, h1, l1);
            *(uint2*)(st + arow * STRA + aseg * 8)        = make_uint2(h0, h1);
            *(uint2*)(st + A_SZ + arow * STRA + aseg * 8) = make_uint2(l0, l1);
            int brow = idx >> 5, bseg = idx & 31;
            split2(bReg[it].x, bReg[it].y, h0, l0);
            split2(bReg[it].z, bReg[it].w, h1, l1);
            *(uint2*)(st + 2 * A_SZ + brow * STRB + bseg * 8)        = make_uint2(h0, h1);
            *(uint2*)(st + 2 * A_SZ + B_SZ + brow * STRB + bseg * 8) = make_uint2(l0, l1);
        }
    };

    float acc[4][4][4] = {};
    int ar = lane & 15, ac = lane >> 4;
    int kr = lane & 7,  sel = lane >> 3;

    auto compute = [&](int buf) {
        uint32_t Ah = sbase + buf * STAGE;
        uint32_t Al = Ah + A_SZ;
        uint32_t Bh = Ah + 2 * A_SZ;
        uint32_t Bl = Bh + B_SZ;
        #pragma unroll
        for (int ks = 0; ks < 2; ks++) {
            uint32_t ah[4][4], al[4][4], bh[8], bl[8];
            #pragma unroll
            for (int mt = 0; mt < 4; mt++) {
                uint32_t off = (uint32_t)((wm * 64 + mt * 16 + ar) * STRA + (ks * 16 + ac * 8) * 2);
                ldsm_x4(ah[mt], Ah + off);
                ldsm_x4(al[mt], Al + off);
            }
            #pragma unroll
            for (int nt2 = 0; nt2 < 2; nt2++) {
                int rowk = ks * 16 + (sel & 1) * 8 + kr;
                int coln = wn * 32 + nt2 * 16 + (sel >> 1) * 8;
                uint32_t off = (uint32_t)(rowk * STRB + coln * 2);
                ldsm_x4t(&bh[nt2 * 4], Bh + off);
                ldsm_x4t(&bl[nt2 * 4], Bl + off);
            }
            #pragma unroll
            for (int mt = 0; mt < 4; mt++)
                #pragma unroll
                for (int nt = 0; nt < 4; nt++) {
                    const uint32_t* bhp = &bh[(nt >> 1) * 4 + (nt & 1) * 2];
                    const uint32_t* blp = &bl[(nt >> 1) * 4 + (nt & 1) * 2];
                    mma16816(acc[mt][nt], ah[mt], bhp);
                    mma16816(acc[mt][nt], ah[mt], blp);
                    mma16816(acc[mt][nt], al[mt], bhp);
                }
        }
    };

    const int NIT = D_FF / BK;   // 64
    ldg(0); sts(0);
    for (int i = 0; i < NIT; i++) {
        __syncthreads();
        if (i + 1 < NIT) ldg((i + 1) * BK);
        compute(i & 1);
        if (i + 1 < NIT) sts((i + 1) & 1);
    }

    // epilogue: + bd, * combine weight, atomic scatter into out
    #pragma unroll
    for (int mt = 0; mt < 4; mt++) {
        int r0 = rowbase + wm * 64 + mt * 16 + (lane >> 2);
        #pragma unroll
        for (int nt = 0; nt < 4; nt++) {
            int c = colbase + wn * 32 + nt * 8 + (lane & 3) * 2;
            float b0 = bd[e * D_MODEL + c], b1 = bd[e * D_MODEL + c + 1];
            if (r0 < n) {
                int t = g_tok[e * TMAX + r0];
                float w = g_wt[e * TMAX + r0];
                atomicAdd(&out[(size_t)t * D_MODEL + c],     w * (acc[mt][nt][0] + b0));
                atomicAdd(&out[(size_t)t * D_MODEL + c + 1], w * (acc[mt][nt][1] + b1));
            }
            if (r0 + 8 < n) {
                int t = g_tok[e * TMAX + r0 + 8];
                float w = g_wt[e * TMAX + r0 + 8];
                atomicAdd(&out[(size_t)t * D_MODEL + c],     w * (acc[mt][nt][2] + b0));
                atomicAdd(&out[(size_t)t * D_MODEL + c + 1], w * (acc[mt][nt][3] + b1));
            }
        }
    }
}

// ---------------------------------------------------------------------------
extern "C" void kernel_launch(void* const* d_in, const int* in_sizes, int n_in,
                              void* d_out, int out_size) {
    const float* x  = (const float*)d_in[0];
    const float* gw = (const float*)d_in[1];
    const float* gb = (const float*)d_in[2];
    const float* Wg = (const float*)d_in[3];
    const float* bg = (const float*)d_in[4];
    const float* Wu = (const float*)d_in[5];
    const float* bu = (const float*)d_in[6];
    const float* Wd = (const float*)d_in[7];
    const float* bd = (const float*)d_in[8];
    float* out = (float*)d_out;

    int T = in_sizes[0] / D_MODEL;   // 2048

    cudaFuncSetAttribute(gu_kernel, cudaFuncAttributeMaxDynamicSharedMemorySize, SMEM_DYN);
    cudaFuncSetAttribute(dn_kernel, cudaFuncAttributeMaxDynamicSharedMemorySize, SMEM_DYN);

    cudaMemsetAsync(out, 0, (size_t)T * D_MODEL * sizeof(float));
    zero_kernel<<<1, 32>>>();
    router_kernel<<<T, 256>>>(x, gw, gb);
    if (out_size > T * D_MODEL) {
        loss_kernel<<<1, 32>>>(out + (size_t)T * D_MODEL, T);
    }
    dim3 g1(2 * D_FF / 128, TMAX / 128, NE);   // 32 x 16 x 8
    gu_kernel<<<g1, 256, SMEM_DYN>>>(x, Wg, bg, Wu, bu);
    dim3 g2(D_MODEL / 128, TMAX / 128, NE);    // 8 x 16 x 8
    dn_kernel<<<g2, 256, SMEM_DYN>>>(Wd, bd, out);
}

// round 6
// speedup vs baseline: 2.8214x; 1.5858x over previous
#include <cuda_runtime.h>
#include <cuda_fp16.h>
#include <math.h>
#include <stdint.h>

#define D_MODEL 1024
#define D_FF    2048
#define NE      8
#define TMAX    2048

#define BK 32
#define STRA 80                      // A smem row stride bytes (128 rows)
#define STRB 272                     // B smem row stride bytes (32 rows)
#define A_SZ (128 * STRA)            // 10240
#define B_SZ (32 * STRB)             // 8704
#define STAGE (2 * A_SZ + 2 * B_SZ)  // 37888 (Ah|Al|Bh|Bl)
#define SMEM_DYN (2 * STAGE)         // 75776

// -------- device scratch (static; no cudaMalloc allowed) --------
__device__ int      g_count[NE];
__device__ double   g_probsum[NE];
__device__ int      g_tok[NE * TMAX];
__device__ float    g_wt[NE * TMAX];
__device__ float    g_G[(size_t)NE * TMAX * D_FF];
__device__ float    g_U[(size_t)NE * TMAX * D_FF];
__device__ uint32_t g_Hp[(size_t)NE * TMAX * D_FF];  // packed (h_hi, h_lo) per elem

// ---------------- helpers ----------------
__device__ __forceinline__ uint32_t smem_u32(const void* p) {
    uint32_t a;
    asm("{ .reg .u64 t; cvta.to.shared.u64 t, %1; cvt.u32.u64 %0, t; }" : "=r"(a) : "l"(p));
    return a;
}
__device__ __forceinline__ void split2(float f0, float f1, uint32_t& hi, uint32_t& lo) {
    __half2 h = __floats2half2_rn(f0, f1);
    float2 hf = __half22float2(h);
    __half2 l = __floats2half2_rn(f0 - hf.x, f1 - hf.y);
    hi = *reinterpret_cast<uint32_t*>(&h);
    lo = *reinterpret_cast<uint32_t*>(&l);
}
__device__ __forceinline__ void ldsm_x4(uint32_t* r, uint32_t addr) {
    asm volatile("ldmatrix.sync.aligned.m8n8.x4.shared.b16 {%0,%1,%2,%3}, [%4];"
                 : "=r"(r[0]), "=r"(r[1]), "=r"(r[2]), "=r"(r[3]) : "r"(addr));
}
__device__ __forceinline__ void ldsm_x4t(uint32_t* r, uint32_t addr) {
    asm volatile("ldmatrix.sync.aligned.m8n8.x4.trans.shared.b16 {%0,%1,%2,%3}, [%4];"
                 : "=r"(r[0]), "=r"(r[1]), "=r"(r[2]), "=r"(r[3]) : "r"(addr));
}
__device__ __forceinline__ void mma16816(float* c, const uint32_t* a, const uint32_t* b) {
    asm volatile("mma.sync.aligned.m16n8k16.row.col.f32.f16.f16.f32 "
                 "{%0,%1,%2,%3}, {%4,%5,%6,%7}, {%8,%9}, {%0,%1,%2,%3};"
                 : "+f"(c[0]), "+f"(c[1]), "+f"(c[2]), "+f"(c[3])
                 : "r"(a[0]), "r"(a[1]), "r"(a[2]), "r"(a[3]), "r"(b[0]), "r"(b[1]));
}

// ---------------------------------------------------------------------------
__global__ void zero_kernel() {
    int i = threadIdx.x;
    if (i < NE) { g_count[i] = 0; g_probsum[i] = 0.0; }
}

__global__ void router_kernel(const float* __restrict__ x,
                              const float* __restrict__ gw,
                              const float* __restrict__ gb) {
    int t    = blockIdx.x;
    int warp = threadIdx.x >> 5;
    int lane = threadIdx.x & 31;
    __shared__ float logits[NE];

    const float* xr = x + (size_t)t * D_MODEL;
    const float* w  = gw + warp * D_MODEL;
    float s = 0.f;
    for (int i = lane; i < D_MODEL; i += 32) s += xr[i] * w[i];
    #pragma unroll
    for (int o = 16; o > 0; o >>= 1) s += __shfl_down_sync(0xffffffff, s, o);
    if (lane == 0) logits[warp] = s + gb[warp];
    __syncthreads();

    if (threadIdx.x == 0) {
        float p[NE];
        float mx = -1e30f;
        #pragma unroll
        for (int e = 0; e < NE; e++) mx = fmaxf(mx, logits[e]);
        float sum = 0.f;
        #pragma unroll
        for (int e = 0; e < NE; e++) { p[e] = expf(logits[e] - mx); sum += p[e]; }
        float inv = 1.f / sum;
        #pragma unroll
        for (int e = 0; e < NE; e++) {
            p[e] *= inv;
            atomicAdd(&g_probsum[e], (double)p[e]);
        }
        int i0 = 0;
        #pragma unroll
        for (int e = 1; e < NE; e++) if (p[e] > p[i0]) i0 = e;
        int i1 = -1;
        #pragma unroll
        for (int e = 0; e < NE; e++) {
            if (e == i0) continue;
            if (i1 < 0 || p[e] > p[i1]) i1 = e;
        }
        float v0 = p[i0], v1 = p[i1];
        float inv2 = 1.f / (v0 + v1);
        int s0 = atomicAdd(&g_count[i0], 1);
        g_tok[i0 * TMAX + s0] = t;  g_wt[i0 * TMAX + s0] = v0 * inv2;
        int s1 = atomicAdd(&g_count[i1], 1);
        g_tok[i1 * TMAX + s1] = t;  g_wt[i1 * TMAX + s1] = v1 * inv2;
    }
}

__global__ void loss_kernel(float* __restrict__ out_loss, int T) {
    if (threadIdx.x == 0) {
        const double ideal = 1.0 / NE;
        double l = 0.0;
        #pragma unroll
        for (int e = 0; e < NE; e++) {
            double mp = g_probsum[e] / (double)T + 1e-9;
            l += ideal * (log(ideal) - log(mp));
        }
        *out_loss = (float)l;
    }
}

// ---------------------------------------------------------------------------
// GU: C = gather(x) @ W + bias -> G or U (fp32 scratch).
// 128x128x32 tile, mma.m16n8k16.f16, 3-term split emulation.
__global__ __launch_bounds__(256)
void gu_kernel(const float* __restrict__ x,
               const float* __restrict__ Wg, const float* __restrict__ bg,
               const float* __restrict__ Wu, const float* __restrict__ bu) {
    int e = blockIdx.z;
    int n = g_count[e];
    int rowbase = blockIdx.y * 128;
    if (rowbase >= n) return;
    bool isU = blockIdx.x >= (D_FF / 128);
    int colbase = (blockIdx.x & (D_FF / 128 - 1)) * 128;

    const float* W    = (isU ? Wu : Wg) + (size_t)e * D_MODEL * D_FF;
    const float* bias = (isU ? bu : bg) + e * D_FF + colbase;
    float*       dst  = (isU ? g_U : g_G) + (size_t)e * TMAX * D_FF;

    extern __shared__ char sm[];
    __shared__ int toks[128];
    uint32_t sbase = smem_u32(sm);

    int tid = threadIdx.x, lane = tid & 31, wid = tid >> 5;
    int wm = wid >> 2, wn = wid & 3;

    if (tid < 128) {
        int r = rowbase + tid;
        toks[tid] = g_tok[e * TMAX + (r < n ? r : n - 1)];
    }
    __syncthreads();

    float4 aReg[4], bReg[4];
    auto ldg = [&](int k0) {
        #pragma unroll
        for (int it = 0; it < 4; it++) {
            int idx = tid + it * 256;
            int arow = idx >> 3, aseg = idx & 7;
            aReg[it] = *(const float4*)(x + (size_t)toks[arow] * D_MODEL + k0 + aseg * 4);
            int brow = idx >> 5, bseg = idx & 31;
            bReg[it] = *(const float4*)(W + (size_t)(k0 + brow) * D_FF + colbase + bseg * 4);
        }
    };
    auto sts = [&](int buf) {
        char* st = sm + buf * STAGE;
        #pragma unroll
        for (int it = 0; it < 4; it++) {
            int idx = tid + it * 256;
            int arow = idx >> 3, aseg = idx & 7;
            uint32_t h0, h1, l0, l1;
            split2(aReg[it].x, aReg[it].y, h0, l0);
            split2(aReg[it].z, aReg[it].w, h1, l1);
            *(uint2*)(st + arow * STRA + aseg * 8)        = make_uint2(h0, h1);
            *(uint2*)(st + A_SZ + arow * STRA + aseg * 8) = make_uint2(l0, l1);
            int brow = idx >> 5, bseg = idx & 31;
            split2(bReg[it].x, bReg[it].y, h0, l0);
            split2(bReg[it].z, bReg[it].w, h1, l1);
            *(uint2*)(st + 2 * A_SZ + brow * STRB + bseg * 8)        = make_uint2(h0, h1);
            *(uint2*)(st + 2 * A_SZ + B_SZ + brow * STRB + bseg * 8) = make_uint2(l0, l1);
        }
    };

    float acc[4][4][4] = {};
    int ar = lane & 15, ac = lane >> 4;          // A ldsm addr parts
    int kr = lane & 7,  sel = lane >> 3;         // B ldsm addr parts

    auto compute = [&](int buf) {
        uint32_t Ah = sbase + buf * STAGE;
        uint32_t Al = Ah + A_SZ;
        uint32_t Bh = Ah + 2 * A_SZ;
        uint32_t Bl = Bh + B_SZ;
        #pragma unroll
        for (int ks = 0; ks < 2; ks++) {
            uint32_t ah[4][4], al[4][4], bh[8], bl[8];
            #pragma unroll
            for (int mt = 0; mt < 4; mt++) {
                uint32_t off = (uint32_t)((wm * 64 + mt * 16 + ar) * STRA + (ks * 16 + ac * 8) * 2);
                ldsm_x4(ah[mt], Ah + off);
                ldsm_x4(al[mt], Al + off);
            }
            #pragma unroll
            for (int nt2 = 0; nt2 < 2; nt2++) {
                int rowk = ks * 16 + (sel & 1) * 8 + kr;
                int coln = wn * 32 + nt2 * 16 + (sel >> 1) * 8;
                uint32_t off = (uint32_t)(rowk * STRB + coln * 2);
                ldsm_x4t(&bh[nt2 * 4], Bh + off);
                ldsm_x4t(&bl[nt2 * 4], Bl + off);
            }
            #pragma unroll
            for (int mt = 0; mt < 4; mt++)
                #pragma unroll
                for (int nt = 0; nt < 4; nt++) {
                    const uint32_t* bhp = &bh[(nt >> 1) * 4 + (nt & 1) * 2];
                    const uint32_t* blp = &bl[(nt >> 1) * 4 + (nt & 1) * 2];
                    mma16816(acc[mt][nt], ah[mt], bhp);
                    mma16816(acc[mt][nt], ah[mt], blp);
                    mma16816(acc[mt][nt], al[mt], bhp);
                }
        }
    };

    const int NIT = D_MODEL / BK;   // 32
    ldg(0); sts(0);
    for (int i = 0; i < NIT; i++) {
        __syncthreads();
        if (i + 1 < NIT) ldg((i + 1) * BK);
        compute(i & 1);
        if (i + 1 < NIT) sts((i + 1) & 1);
    }

    // epilogue: acc + bias -> dst (fp32)
    #pragma unroll
    for (int mt = 0; mt < 4; mt++) {
        int r0 = rowbase + wm * 64 + mt * 16 + (lane >> 2);
        #pragma unroll
        for (int nt = 0; nt < 4; nt++) {
            int c = wn * 32 + nt * 8 + (lane & 3) * 2;
            float b0 = bias[c], b1 = bias[c + 1];
            if (r0 < n) {
                float* p = dst + (size_t)r0 * D_FF + colbase + c;
                p[0] = acc[mt][nt][0] + b0;
                p[1] = acc[mt][nt][1] + b1;
            }
            if (r0 + 8 < n) {
                float* p = dst + (size_t)(r0 + 8) * D_FF + colbase + c;
                p[0] = acc[mt][nt][2] + b0;
                p[1] = acc[mt][nt][3] + b1;
            }
        }
    }
}

// ---------------------------------------------------------------------------
// pack_h: h = silu(G)*U, stored as packed (fp16 hi, fp16 lo) uint32.
__global__ __launch_bounds__(256)
void pack_h_kernel() {
    int e = blockIdx.z;
    int r = blockIdx.y;
    if (r >= g_count[e]) return;
    int c = blockIdx.x * 1024 + threadIdx.x * 4;
    size_t o = ((size_t)e * TMAX + r) * D_FF + c;
    float4 g = *(const float4*)(g_G + o);
    float4 u = *(const float4*)(g_U + o);
    float h0 = g.x / (1.f + __expf(-g.x)) * u.x;
    float h1 = g.y / (1.f + __expf(-g.y)) * u.y;
    float h2 = g.z / (1.f + __expf(-g.z)) * u.z;
    float h3 = g.w / (1.f + __expf(-g.w)) * u.w;
    uint32_t hi01, lo01, hi23, lo23;
    split2(h0, h1, hi01, lo01);
    split2(h2, h3, hi23, lo23);
    uint4 v;
    v.x = __byte_perm(hi01, lo01, 0x5410);   // (h0_hi, h0_lo)
    v.y = __byte_perm(hi01, lo01, 0x7632);   // (h1_hi, h1_lo)
    v.z = __byte_perm(hi23, lo23, 0x5410);
    v.w = __byte_perm(hi23, lo23, 0x7632);
    *(uint4*)(g_Hp + o) = v;
}

// ---------------------------------------------------------------------------
// Down: out[t] += w * ( H @ Wd + bd ), A staged from packed H, split-K=2.
__global__ __launch_bounds__(256)
void dn_kernel(const float* __restrict__ Wd, const float* __restrict__ bd,
               float* __restrict__ out) {
    int e  = blockIdx.z >> 1;
    int kb = blockIdx.z & 1;
    int n = g_count[e];
    int rowbase = blockIdx.y * 128;
    if (rowbase >= n) return;
    int colbase = blockIdx.x * 128;
    int kbase = kb * (D_FF / 2);

    const float*    W  = Wd + (size_t)e * D_FF * D_MODEL;
    const uint32_t* Hp = g_Hp + (size_t)e * TMAX * D_FF;

    extern __shared__ char sm[];
    uint32_t sbase = smem_u32(sm);

    int tid = threadIdx.x, lane = tid & 31, wid = tid >> 5;
    int wm = wid >> 2, wn = wid & 3;

    uint4  aReg[4];
    float4 bReg[4];
    auto ldg = [&](int k0) {
        #pragma unroll
        for (int it = 0; it < 4; it++) {
            int idx = tid + it * 256;
            int arow = idx >> 3, aseg = idx & 7;
            int r = rowbase + arow; if (r >= n) r = n - 1;
            aReg[it] = *(const uint4*)(Hp + (size_t)r * D_FF + kbase + k0 + aseg * 4);
            int brow = idx >> 5, bseg = idx & 31;
            bReg[it] = *(const float4*)(W + (size_t)(kbase + k0 + brow) * D_MODEL + colbase + bseg * 4);
        }
    };
    auto sts = [&](int buf) {
        char* st = sm + buf * STAGE;
        #pragma unroll
        for (int it = 0; it < 4; it++) {
            int idx = tid + it * 256;
            int arow = idx >> 3, aseg = idx & 7;
            uint32_t h01 = __byte_perm(aReg[it].x, aReg[it].y, 0x5410);
            uint32_t l01 = __byte_perm(aReg[it].x, aReg[it].y, 0x7632);
            uint32_t h23 = __byte_perm(aReg[it].z, aReg[it].w, 0x5410);
            uint32_t l23 = __byte_perm(aReg[it].z, aReg[it].w, 0x7632);
            *(uint2*)(st + arow * STRA + aseg * 8)        = make_uint2(h01, h23);
            *(uint2*)(st + A_SZ + arow * STRA + aseg * 8) = make_uint2(l01, l23);
            int brow = idx >> 5, bseg = idx & 31;
            uint32_t bh0, bh1, bl0, bl1;
            split2(bReg[it].x, bReg[it].y, bh0, bl0);
            split2(bReg[it].z, bReg[it].w, bh1, bl1);
            *(uint2*)(st + 2 * A_SZ + brow * STRB + bseg * 8)        = make_uint2(bh0, bh1);
            *(uint2*)(st + 2 * A_SZ + B_SZ + brow * STRB + bseg * 8) = make_uint2(bl0, bl1);
        }
    };

    float acc[4][4][4] = {};
    int ar = lane & 15, ac = lane >> 4;
    int kr = lane & 7,  sel = lane >> 3;

    auto compute = [&](int buf) {
        uint32_t Ah = sbase + buf * STAGE;
        uint32_t Al = Ah + A_SZ;
        uint32_t Bh = Ah + 2 * A_SZ;
        uint32_t Bl = Bh + B_SZ;
        #pragma unroll
        for (int ks = 0; ks < 2; ks++) {
            uint32_t ah[4][4], al[4][4], bh[8], bl[8];
            #pragma unroll
            for (int mt = 0; mt < 4; mt++) {
                uint32_t off = (uint32_t)((wm * 64 + mt * 16 + ar) * STRA + (ks * 16 + ac * 8) * 2);
                ldsm_x4(ah[mt], Ah + off);
                ldsm_x4(al[mt], Al + off);
            }
            #pragma unroll
            for (int nt2 = 0; nt2 < 2; nt2++) {
                int rowk = ks * 16 + (sel & 1) * 8 + kr;
                int coln = wn * 32 + nt2 * 16 + (sel >> 1) * 8;
                uint32_t off = (uint32_t)(rowk * STRB + coln * 2);
                ldsm_x4t(&bh[nt2 * 4], Bh + off);
                ldsm_x4t(&bl[nt2 * 4], Bl + off);
            }
            #pragma unroll
            for (int mt = 0; mt < 4; mt++)
                #pragma unroll
                for (int nt = 0; nt < 4; nt++) {
                    const uint32_t* bhp = &bh[(nt >> 1) * 4 + (nt & 1) * 2];
                    const uint32_t* blp = &bl[(nt >> 1) * 4 + (nt & 1) * 2];
                    mma16816(acc[mt][nt], ah[mt], bhp);
                    mma16816(acc[mt][nt], ah[mt], blp);
                    mma16816(acc[mt][nt], al[mt], bhp);
                }
        }
    };

    const int NIT = (D_FF / 2) / BK;   // 32
    ldg(0); sts(0);
    for (int i = 0; i < NIT; i++) {
        __syncthreads();
        if (i + 1 < NIT) ldg((i + 1) * BK);
        compute(i & 1);
        if (i + 1 < NIT) sts((i + 1) & 1);
    }

    // epilogue: + bd (kb==0 only), * combine weight, atomic scatter into out
    #pragma unroll
    for (int mt = 0; mt < 4; mt++) {
        int r0 = rowbase + wm * 64 + mt * 16 + (lane >> 2);
        #pragma unroll
        for (int nt = 0; nt < 4; nt++) {
            int c = colbase + wn * 32 + nt * 8 + (lane & 3) * 2;
            float b0 = 0.f, b1 = 0.f;
            if (kb == 0) { b0 = bd[e * D_MODEL + c]; b1 = bd[e * D_MODEL + c + 1]; }
            if (r0 < n) {
                int t = g_tok[e * TMAX + r0];
                float w = g_wt[e * TMAX + r0];
                atomicAdd(&out[(size_t)t * D_MODEL + c],     w * (acc[mt][nt][0] + b0));
                atomicAdd(&out[(size_t)t * D_MODEL + c + 1], w * (acc[mt][nt][1] + b1));
            }
            if (r0 + 8 < n) {
                int t = g_tok[e * TMAX + r0 + 8];
                float w = g_wt[e * TMAX + r0 + 8];
                atomicAdd(&out[(size_t)t * D_MODEL + c],     w * (acc[mt][nt][2] + b0));
                atomicAdd(&out[(size_t)t * D_MODEL + c + 1], w * (acc[mt][nt][3] + b1));
            }
        }
    }
}

// ---------------------------------------------------------------------------
extern "C" void kernel_launch(void* const* d_in, const int* in_sizes, int n_in,
                              void* d_out, int out_size) {
    const float* x  = (const float*)d_in[0];
    const float* gw = (const float*)d_in[1];
    const float* gb = (const float*)d_in[2];
    const float* Wg = (const float*)d_in[3];
    const float* bg = (const float*)d_in[4];
    const float* Wu = (const float*)d_in[5];
    const float* bu = (const float*)d_in[6];
    const float* Wd = (const float*)d_in[7];
    const float* bd = (const float*)d_in[8];
    float* out = (float*)d_out;

    int T = in_sizes[0] / D_MODEL;   // 2048

    cudaFuncSetAttribute(gu_kernel, cudaFuncAttributeMaxDynamicSharedMemorySize, SMEM_DYN);
    cudaFuncSetAttribute(dn_kernel, cudaFuncAttributeMaxDynamicSharedMemorySize, SMEM_DYN);

    cudaMemsetAsync(out, 0, (size_t)T * D_MODEL * sizeof(float));
    zero_kernel<<<1, 32>>>();
    router_kernel<<<T, 256>>>(x, gw, gb);
    if (out_size > T * D_MODEL) {
        loss_kernel<<<1, 32>>>(out + (size_t)T * D_MODEL, T);
    }
    dim3 g1(2 * D_FF / 128, TMAX / 128, NE);   // 32 x 16 x 8
    gu_kernel<<<g1, 256, SMEM_DYN>>>(x, Wg, bg, Wu, bu);
    dim3 gp(D_FF / 1024, TMAX, NE);            // 2 x 2048 x 8
    pack_h_kernel<<<gp, 256>>>();
    dim3 g2(D_MODEL / 128, TMAX / 128, NE * 2); // 8 x 16 x 16 (split-K=2)
    dn_kernel<<<g2, 256, SMEM_DYN>>>(Wd, bd, out);
}

// round 8
// speedup vs baseline: 4.1684x; 1.4774x over previous
#include <cuda_runtime.h>
#include <cuda_fp16.h>
#include <math.h>
#include <stdint.h>

#define D_MODEL 1024
#define D_FF    2048
#define NE      8
#define TMAX    2048

#define BK 32
#define STRA 80                      // A smem row stride bytes (128 rows)
#define STRB 272                     // B smem row stride bytes (32 rows)
#define A_SZ (128 * STRA)            // 10240
#define B_SZ (32 * STRB)             // 8704
#define STAGE (A_SZ + 2 * B_SZ)      // 27648 (Ah|Bh|Bl)
#define SMEM_DYN (2 * STAGE)         // 55296

// -------- device scratch (static; no cudaMalloc allowed) --------
__device__ int      g_count[NE];
__device__ double   g_probsum[NE];
__device__ int      g_tok[NE * TMAX];
__device__ float    g_wt[NE * TMAX];
__device__ float    g_G[(size_t)NE * TMAX * D_FF];
__device__ float    g_U[(size_t)NE * TMAX * D_FF];
__device__ uint32_t g_Hp[(size_t)NE * TMAX * D_FF / 2];  // fp16 h, half2-packed

// ---------------- helpers ----------------
__device__ __forceinline__ uint32_t smem_u32(const void* p) {
    uint32_t a;
    asm("{ .reg .u64 t; cvta.to.shared.u64 t, %1; cvt.u32.u64 %0, t; }" : "=r"(a) : "l"(p));
    return a;
}
__device__ __forceinline__ void split2(float f0, float f1, uint32_t& hi, uint32_t& lo) {
    __half2 h = __floats2half2_rn(f0, f1);
    float2 hf = __half22float2(h);
    __half2 l = __floats2half2_rn(f0 - hf.x, f1 - hf.y);
    hi = *reinterpret_cast<uint32_t*>(&h);
    lo = *reinterpret_cast<uint32_t*>(&l);
}
__device__ __forceinline__ uint32_t cvt2(float f0, float f1) {
    __half2 h = __floats2half2_rn(f0, f1);
    return *reinterpret_cast<uint32_t*>(&h);
}
__device__ __forceinline__ void ldsm_x4(uint32_t* r, uint32_t addr) {
    asm volatile("ldmatrix.sync.aligned.m8n8.x4.shared.b16 {%0,%1,%2,%3}, [%4];"
                 : "=r"(r[0]), "=r"(r[1]), "=r"(r[2]), "=r"(r[3]) : "r"(addr));
}
__device__ __forceinline__ void ldsm_x4t(uint32_t* r, uint32_t addr) {
    asm volatile("ldmatrix.sync.aligned.m8n8.x4.trans.shared.b16 {%0,%1,%2,%3}, [%4];"
                 : "=r"(r[0]), "=r"(r[1]), "=r"(r[2]), "=r"(r[3]) : "r"(addr));
}
__device__ __forceinline__ void mma16816(float* c, const uint32_t* a, const uint32_t* b) {
    asm volatile("mma.sync.aligned.m16n8k16.row.col.f32.f16.f16.f32 "
                 "{%0,%1,%2,%3}, {%4,%5,%6,%7}, {%8,%9}, {%0,%1,%2,%3};"
                 : "+f"(c[0]), "+f"(c[1]), "+f"(c[2]), "+f"(c[3])
                 : "r"(a[0]), "r"(a[1]), "r"(a[2]), "r"(a[3]), "r"(b[0]), "r"(b[1]));
}

// ---------------------------------------------------------------------------
__global__ void zero_kernel() {
    int i = threadIdx.x;
    if (i < NE) { g_count[i] = 0; g_probsum[i] = 0.0; }
}

__global__ void router_kernel(const float* __restrict__ x,
                              const float* __restrict__ gw,
                              const float* __restrict__ gb) {
    int t    = blockIdx.x;
    int warp = threadIdx.x >> 5;
    int lane = threadIdx.x & 31;
    __shared__ float logits[NE];

    const float* xr = x + (size_t)t * D_MODEL;
    const float* w  = gw + warp * D_MODEL;
    float s = 0.f;
    for (int i = lane; i < D_MODEL; i += 32) s += xr[i] * w[i];
    #pragma unroll
    for (int o = 16; o > 0; o >>= 1) s += __shfl_down_sync(0xffffffff, s, o);
    if (lane == 0) logits[warp] = s + gb[warp];
    __syncthreads();

    if (threadIdx.x == 0) {
        float p[NE];
        float mx = -1e30f;
        #pragma unroll
        for (int e = 0; e < NE; e++) mx = fmaxf(mx, logits[e]);
        float sum = 0.f;
        #pragma unroll
        for (int e = 0; e < NE; e++) { p[e] = expf(logits[e] - mx); sum += p[e]; }
        float inv = 1.f / sum;
        #pragma unroll
        for (int e = 0; e < NE; e++) {
            p[e] *= inv;
            atomicAdd(&g_probsum[e], (double)p[e]);
        }
        int i0 = 0;
        #pragma unroll
        for (int e = 1; e < NE; e++) if (p[e] > p[i0]) i0 = e;
        int i1 = -1;
        #pragma unroll
        for (int e = 0; e < NE; e++) {
            if (e == i0) continue;
            if (i1 < 0 || p[e] > p[i1]) i1 = e;
        }
        float v0 = p[i0], v1 = p[i1];
        float inv2 = 1.f / (v0 + v1);
        int s0 = atomicAdd(&g_count[i0], 1);
        g_tok[i0 * TMAX + s0] = t;  g_wt[i0 * TMAX + s0] = v0 * inv2;
        int s1 = atomicAdd(&g_count[i1], 1);
        g_tok[i1 * TMAX + s1] = t;  g_wt[i1 * TMAX + s1] = v1 * inv2;
    }
}

__global__ void loss_kernel(float* __restrict__ out_loss, int T) {
    if (threadIdx.x == 0) {
        const double ideal = 1.0 / NE;
        double l = 0.0;
        #pragma unroll
        for (int e = 0; e < NE; e++) {
            double mp = g_probsum[e] / (double)T + 1e-9;
            l += ideal * (log(ideal) - log(mp));
        }
        *out_loss = (float)l;
    }
}

// ---------------------------------------------------------------------------
// GU: C = gather(x) @ W + bias -> G or U (fp32 scratch).
// 128x128x32 tile, mma.m16n8k16.f16; A fp16, B 2-term split.
__global__ __launch_bounds__(256, 2)
void gu_kernel(const float* __restrict__ x,
               const float* __restrict__ Wg, const float* __restrict__ bg,
               const float* __restrict__ Wu, const float* __restrict__ bu) {
    int e = blockIdx.z;
    int n = g_count[e];
    int rowbase = blockIdx.y * 128;
    if (rowbase >= n) return;
    bool isU = blockIdx.x >= (D_FF / 128);
    int colbase = (blockIdx.x & (D_FF / 128 - 1)) * 128;

    const float* W    = (isU ? Wu : Wg) + (size_t)e * D_MODEL * D_FF;
    const float* bias = (isU ? bu : bg) + e * D_FF + colbase;
    float*       dst  = (isU ? g_U : g_G) + (size_t)e * TMAX * D_FF;

    extern __shared__ char sm[];
    __shared__ int toks[128];
    uint32_t sbase = smem_u32(sm);

    int tid = threadIdx.x, lane = tid & 31, wid = tid >> 5;
    int wm = wid >> 2, wn = wid & 3;

    if (tid < 128) {
        int r = rowbase + tid;
        toks[tid] = g_tok[e * TMAX + (r < n ? r : n - 1)];
    }
    __syncthreads();

    float4 aReg[4], bReg[4];
    auto ldg = [&](int k0) {
        #pragma unroll
        for (int it = 0; it < 4; it++) {
            int idx = tid + it * 256;
            int arow = idx >> 3, aseg = idx & 7;
            aReg[it] = *(const float4*)(x + (size_t)toks[arow] * D_MODEL + k0 + aseg * 4);
            int brow = idx >> 5, bseg = idx & 31;
            bReg[it] = *(const float4*)(W + (size_t)(k0 + brow) * D_FF + colbase + bseg * 4);
        }
    };
    auto sts = [&](int buf) {
        char* st = sm + buf * STAGE;
        #pragma unroll
        for (int it = 0; it < 4; it++) {
            int idx = tid + it * 256;
            int arow = idx >> 3, aseg = idx & 7;
            uint32_t a01 = cvt2(aReg[it].x, aReg[it].y);
            uint32_t a23 = cvt2(aReg[it].z, aReg[it].w);
            *(uint2*)(st + arow * STRA + aseg * 8) = make_uint2(a01, a23);
            int brow = idx >> 5, bseg = idx & 31;
            uint32_t bh0, bh1, bl0, bl1;
            split2(bReg[it].x, bReg[it].y, bh0, bl0);
            split2(bReg[it].z, bReg[it].w, bh1, bl1);
            *(uint2*)(st + A_SZ + brow * STRB + bseg * 8)        = make_uint2(bh0, bh1);
            *(uint2*)(st + A_SZ + B_SZ + brow * STRB + bseg * 8) = make_uint2(bl0, bl1);
        }
    };

    float acc[4][4][4] = {};
    int ar = lane & 15, ac = lane >> 4;          // A ldsm addr parts
    int kr = lane & 7,  sel = lane >> 3;         // B ldsm addr parts

    auto compute = [&](int buf) {
        uint32_t Ah = sbase + buf * STAGE;
        uint32_t Bh = Ah + A_SZ;
        uint32_t Bl = Bh + B_SZ;
        #pragma unroll
        for (int ks = 0; ks < 2; ks++) {
            uint32_t ah[4][4], bh[8], bl[8];
            #pragma unroll
            for (int mt = 0; mt < 4; mt++) {
                uint32_t off = (uint32_t)((wm * 64 + mt * 16 + ar) * STRA + (ks * 16 + ac * 8) * 2);
                ldsm_x4(ah[mt], Ah + off);
            }
            #pragma unroll
            for (int nt2 = 0; nt2 < 2; nt2++) {
                int rowk = ks * 16 + (sel & 1) * 8 + kr;
                int coln = wn * 32 + nt2 * 16 + (sel >> 1) * 8;
                uint32_t off = (uint32_t)(rowk * STRB + coln * 2);
                ldsm_x4t(&bh[nt2 * 4], Bh + off);
                ldsm_x4t(&bl[nt2 * 4], Bl + off);
            }
            #pragma unroll
            for (int mt = 0; mt < 4; mt++)
                #pragma unroll
                for (int nt = 0; nt < 4; nt++) {
                    const uint32_t* bhp = &bh[(nt >> 1) * 4 + (nt & 1) * 2];
                    const uint32_t* blp = &bl[(nt >> 1) * 4 + (nt & 1) * 2];
                    mma16816(acc[mt][nt], ah[mt], bhp);
                    mma16816(acc[mt][nt], ah[mt], blp);
                }
        }
    };

    const int NIT = D_MODEL / BK;   // 32
    ldg(0); sts(0);
    for (int i = 0; i < NIT; i++) {
        __syncthreads();
        if (i + 1 < NIT) ldg((i + 1) * BK);
        compute(i & 1);
        if (i + 1 < NIT) sts((i + 1) & 1);
    }

    // epilogue: acc + bias -> dst (fp32)
    #pragma unroll
    for (int mt = 0; mt < 4; mt++) {
        int r0 = rowbase + wm * 64 + mt * 16 + (lane >> 2);
        #pragma unroll
        for (int nt = 0; nt < 4; nt++) {
            int c = wn * 32 + nt * 8 + (lane & 3) * 2;
            float b0 = bias[c], b1 = bias[c + 1];
            if (r0 < n) {
                float* p = dst + (size_t)r0 * D_FF + colbase + c;
                p[0] = acc[mt][nt][0] + b0;
                p[1] = acc[mt][nt][1] + b1;
            }
            if (r0 + 8 < n) {
                float* p = dst + (size_t)(r0 + 8) * D_FF + colbase + c;
                p[0] = acc[mt][nt][2] + b0;
                p[1] = acc[mt][nt][3] + b1;
            }
        }
    }
}

// ---------------------------------------------------------------------------
// pack_h: h = silu(G)*U, stored as fp16 half2-packed.
__global__ __launch_bounds__(256)
void pack_h_kernel() {
    int e = blockIdx.z;
    int r = blockIdx.y;
    if (r >= g_count[e]) return;
    int c = blockIdx.x * 1024 + threadIdx.x * 4;
    size_t o = ((size_t)e * TMAX + r) * D_FF + c;
    float4 g = *(const float4*)(g_G + o);
    float4 u = *(const float4*)(g_U + o);
    float h0 = g.x / (1.f + __expf(-g.x)) * u.x;
    float h1 = g.y / (1.f + __expf(-g.y)) * u.y;
    float h2 = g.z / (1.f + __expf(-g.z)) * u.z;
    float h3 = g.w / (1.f + __expf(-g.w)) * u.w;
    uint2 v;
    v.x = cvt2(h0, h1);
    v.y = cvt2(h2, h3);
    *(uint2*)(g_Hp + o / 2) = v;
}

// ---------------------------------------------------------------------------
// Down: out[t] += w * ( H @ Wd + bd ), A = fp16 H (copy), B split, split-K=2.
__global__ __launch_bounds__(256, 2)
void dn_kernel(const float* __restrict__ Wd, const float* __restrict__ bd,
               float* __restrict__ out) {
    int e  = blockIdx.z >> 1;
    int kb = blockIdx.z & 1;
    int n = g_count[e];
    int rowbase = blockIdx.y * 128;
    if (rowbase >= n) return;
    int colbase = blockIdx.x * 128;
    int kbase = kb * (D_FF / 2);

    const float*    W  = Wd + (size_t)e * D_FF * D_MODEL;
    const uint32_t* Hp = g_Hp + (size_t)e * TMAX * (D_FF / 2);

    extern __shared__ char sm[];
    uint32_t sbase = smem_u32(sm);

    int tid = threadIdx.x, lane = tid & 31, wid = tid >> 5;
    int wm = wid >> 2, wn = wid & 3;

    uint2  aReg[4];
    float4 bReg[4];
    auto ldg = [&](int k0) {
        #pragma unroll
        for (int it = 0; it < 4; it++) {
            int idx = tid + it * 256;
            int arow = idx >> 3, aseg = idx & 7;
            int r = rowbase + arow; if (r >= n) r = n - 1;
            // 4 halves per aseg step: offset aseg*2 uint32s within this k-tile
            aReg[it] = *(const uint2*)(Hp + (size_t)r * (D_FF / 2) + ((kbase + k0) >> 1) + aseg * 2);
            int brow = idx >> 5, bseg = idx & 31;
            bReg[it] = *(const float4*)(W + (size_t)(kbase + k0 + brow) * D_MODEL + colbase + bseg * 4);
        }
    };
    auto sts = [&](int buf) {
        char* st = sm + buf * STAGE;
        #pragma unroll
        for (int it = 0; it < 4; it++) {
            int idx = tid + it * 256;
            int arow = idx >> 3, aseg = idx & 7;
            *(uint2*)(st + arow * STRA + aseg * 8) = aReg[it];
            int brow = idx >> 5, bseg = idx & 31;
            uint32_t bh0, bh1, bl0, bl1;
            split2(bReg[it].x, bReg[it].y, bh0, bl0);
            split2(bReg[it].z, bReg[it].w, bh1, bl1);
            *(uint2*)(st + A_SZ + brow * STRB + bseg * 8)        = make_uint2(bh0, bh1);
            *(uint2*)(st + A_SZ + B_SZ + brow * STRB + bseg * 8) = make_uint2(bl0, bl1);
        }
    };

    float acc[4][4][4] = {};
    int ar = lane & 15, ac = lane >> 4;
    int kr = lane & 7,  sel = lane >> 3;

    auto compute = [&](int buf) {
        uint32_t Ah = sbase + buf * STAGE;
        uint32_t Bh = Ah + A_SZ;
        uint32_t Bl = Bh + B_SZ;
        #pragma unroll
        for (int ks = 0; ks < 2; ks++) {
            uint32_t ah[4][4], bh[8], bl[8];
            #pragma unroll
            for (int mt = 0; mt < 4; mt++) {
                uint32_t off = (uint32_t)((wm * 64 + mt * 16 + ar) * STRA + (ks * 16 + ac * 8) * 2);
                ldsm_x4(ah[mt], Ah + off);
            }
            #pragma unroll
            for (int nt2 = 0; nt2 < 2; nt2++) {
                int rowk = ks * 16 + (sel & 1) * 8 + kr;
                int coln = wn * 32 + nt2 * 16 + (sel >> 1) * 8;
                uint32_t off = (uint32_t)(rowk * STRB + coln * 2);
                ldsm_x4t(&bh[nt2 * 4], Bh + off);
                ldsm_x4t(&bl[nt2 * 4], Bl + off);
            }
            #pragma unroll
            for (int mt = 0; mt < 4; mt++)
                #pragma unroll
                for (int nt = 0; nt < 4; nt++) {
                    const uint32_t* bhp = &bh[(nt >> 1) * 4 + (nt & 1) * 2];
                    const uint32_t* blp = &bl[(nt >> 1) * 4 + (nt & 1) * 2];
                    mma16816(acc[mt][nt], ah[mt], bhp);
                    mma16816(acc[mt][nt], ah[mt], blp);
                }
        }
    };

    const int NIT = (D_FF / 2) / BK;   // 32
    ldg(0); sts(0);
    for (int i = 0; i < NIT; i++) {
        __syncthreads();
        if (i + 1 < NIT) ldg((i + 1) * BK);
        compute(i & 1);
        if (i + 1 < NIT) sts((i + 1) & 1);
    }

    // epilogue: + bd (kb==0 only), * combine weight, atomic scatter into out
    #pragma unroll
    for (int mt = 0; mt < 4; mt++) {
        int r0 = rowbase + wm * 64 + mt * 16 + (lane >> 2);
        #pragma unroll
        for (int nt = 0; nt < 4; nt++) {
            int c = colbase + wn * 32 + nt * 8 + (lane & 3) * 2;
            float b0 = 0.f, b1 = 0.f;
            if (kb == 0) { b0 = bd[e * D_MODEL + c]; b1 = bd[e * D_MODEL + c + 1]; }
            if (r0 < n) {
                int t = g_tok[e * TMAX + r0];
                float w = g_wt[e * TMAX + r0];
                atomicAdd(&out[(size_t)t * D_MODEL + c],     w * (acc[mt][nt][0] + b0));
                atomicAdd(&out[(size_t)t * D_MODEL + c + 1], w * (acc[mt][nt][1] + b1));
            }
            if (r0 + 8 < n) {
                int t = g_tok[e * TMAX + r0 + 8];
                float w = g_wt[e * TMAX + r0 + 8];
                atomicAdd(&out[(size_t)t * D_MODEL + c],     w * (acc[mt][nt][2] + b0));
                atomicAdd(&out[(size_t)t * D_MODEL + c + 1], w * (acc[mt][nt][3] + b1));
            }
        }
    }
}

// ---------------------------------------------------------------------------
extern "C" void kernel_launch(void* const* d_in, const int* in_sizes, int n_in,
                              void* d_out, int out_size) {
    const float* x  = (const float*)d_in[0];
    const float* gw = (const float*)d_in[1];
    const float* gb = (const float*)d_in[2];
    const float* Wg = (const float*)d_in[3];
    const float* bg = (const float*)d_in[4];
    const float* Wu = (const float*)d_in[5];
    const float* bu = (const float*)d_in[6];
    const float* Wd = (const float*)d_in[7];
    const float* bd = (const float*)d_in[8];
    float* out = (float*)d_out;

    int T = in_sizes[0] / D_MODEL;   // 2048

    cudaFuncSetAttribute(gu_kernel, cudaFuncAttributeMaxDynamicSharedMemorySize, SMEM_DYN);
    cudaFuncSetAttribute(dn_kernel, cudaFuncAttributeMaxDynamicSharedMemorySize, SMEM_DYN);

    cudaMemsetAsync(out, 0, (size_t)T * D_MODEL * sizeof(float));
    zero_kernel<<<1, 32>>>();
    router_kernel<<<T, 256>>>(x, gw, gb);
    if (out_size > T * D_MODEL) {
        loss_kernel<<<1, 32>>>(out + (size_t)T * D_MODEL, T);
    }
    dim3 g1(2 * D_FF / 128, TMAX / 128, NE);   // 32 x 16 x 8
    gu_kernel<<<g1, 256, SMEM_DYN>>>(x, Wg, bg, Wu, bu);
    dim3 gp(D_FF / 1024, TMAX, NE);            // 2 x 2048 x 8
    pack_h_kernel<<<gp, 256>>>();
    dim3 g2(D_MODEL / 128, TMAX / 128, NE * 2); // 8 x 16 x 16 (split-K=2)
    dn_kernel<<<g2, 256, SMEM_DYN>>>(Wd, bd, out);
}

// round 9
// speedup vs baseline: 4.3655x; 1.0473x over previous
#include <cuda_runtime.h>
#include <cuda_fp16.h>
#include <math.h>
#include <stdint.h>

#define D_MODEL 1024
#define D_FF    2048
#define NE      8
#define TMAX    2048

#define BK 32
#define STRA 80                       // A smem row stride bytes (128 rows)
// fused GU kernel: B tiles are 32 krows x 64 cols fp16
#define STRB2 144                     // B smem row stride bytes (fused, 64 cols)
#define B2_SZ (32 * STRB2)            // 4608
#define A_SZ (128 * STRA)             // 10240
#define STAGE_GU (A_SZ + 4 * B2_SZ)   // 28672 (A | Bg_h | Bg_l | Bu_h | Bu_l)
#define GU_DYN (2 * STAGE_GU)         // 57344
// dn kernel: B tiles are 32 krows x 128 cols fp16
#define STRB 272
#define B_SZ (32 * STRB)              // 8704
#define STAGE_DN (A_SZ + 2 * B_SZ)    // 27648 (A | Bh | Bl)
#define DN_DYN (2 * STAGE_DN)         // 55296

// -------- device scratch (static; no cudaMalloc allowed) --------
__device__ int      g_count[NE];
__device__ double   g_probsum[NE];
__device__ int      g_tok[NE * TMAX];
__device__ float    g_wt[NE * TMAX];
__device__ uint32_t g_Hp[(size_t)NE * TMAX * D_FF / 2];  // fp16 h, half2-packed

// ---------------- helpers ----------------
__device__ __forceinline__ uint32_t smem_u32(const void* p) {
    uint32_t a;
    asm("{ .reg .u64 t; cvta.to.shared.u64 t, %1; cvt.u32.u64 %0, t; }" : "=r"(a) : "l"(p));
    return a;
}
__device__ __forceinline__ void split2(float f0, float f1, uint32_t& hi, uint32_t& lo) {
    __half2 h = __floats2half2_rn(f0, f1);
    float2 hf = __half22float2(h);
    __half2 l = __floats2half2_rn(f0 - hf.x, f1 - hf.y);
    hi = *reinterpret_cast<uint32_t*>(&h);
    lo = *reinterpret_cast<uint32_t*>(&l);
}
__device__ __forceinline__ uint32_t cvt2(float f0, float f1) {
    __half2 h = __floats2half2_rn(f0, f1);
    return *reinterpret_cast<uint32_t*>(&h);
}
__device__ __forceinline__ void ldsm_x4(uint32_t* r, uint32_t addr) {
    asm volatile("ldmatrix.sync.aligned.m8n8.x4.shared.b16 {%0,%1,%2,%3}, [%4];"
                 : "=r"(r[0]), "=r"(r[1]), "=r"(r[2]), "=r"(r[3]) : "r"(addr));
}
__device__ __forceinline__ void ldsm_x4t(uint32_t* r, uint32_t addr) {
    asm volatile("ldmatrix.sync.aligned.m8n8.x4.trans.shared.b16 {%0,%1,%2,%3}, [%4];"
                 : "=r"(r[0]), "=r"(r[1]), "=r"(r[2]), "=r"(r[3]) : "r"(addr));
}
__device__ __forceinline__ void mma16816(float* c, const uint32_t* a, const uint32_t* b) {
    asm volatile("mma.sync.aligned.m16n8k16.row.col.f32.f16.f16.f32 "
                 "{%0,%1,%2,%3}, {%4,%5,%6,%7}, {%8,%9}, {%0,%1,%2,%3};"
                 : "+f"(c[0]), "+f"(c[1]), "+f"(c[2]), "+f"(c[3])
                 : "r"(a[0]), "r"(a[1]), "r"(a[2]), "r"(a[3]), "r"(b[0]), "r"(b[1]));
}

// ---------------------------------------------------------------------------
__global__ void zero_kernel() {
    int i = threadIdx.x;
    if (i < NE) { g_count[i] = 0; g_probsum[i] = 0.0; }
}

__global__ void router_kernel(const float* __restrict__ x,
                              const float* __restrict__ gw,
                              const float* __restrict__ gb) {
    int t    = blockIdx.x;
    int warp = threadIdx.x >> 5;
    int lane = threadIdx.x & 31;
    __shared__ float logits[NE];

    const float* xr = x + (size_t)t * D_MODEL;
    const float* w  = gw + warp * D_MODEL;
    float s = 0.f;
    for (int i = lane; i < D_MODEL; i += 32) s += xr[i] * w[i];
    #pragma unroll
    for (int o = 16; o > 0; o >>= 1) s += __shfl_down_sync(0xffffffff, s, o);
    if (lane == 0) logits[warp] = s + gb[warp];
    __syncthreads();

    if (threadIdx.x == 0) {
        float p[NE];
        float mx = -1e30f;
        #pragma unroll
        for (int e = 0; e < NE; e++) mx = fmaxf(mx, logits[e]);
        float sum = 0.f;
        #pragma unroll
        for (int e = 0; e < NE; e++) { p[e] = expf(logits[e] - mx); sum += p[e]; }
        float inv = 1.f / sum;
        #pragma unroll
        for (int e = 0; e < NE; e++) {
            p[e] *= inv;
            atomicAdd(&g_probsum[e], (double)p[e]);
        }
        int i0 = 0;
        #pragma unroll
        for (int e = 1; e < NE; e++) if (p[e] > p[i0]) i0 = e;
        int i1 = -1;
        #pragma unroll
        for (int e = 0; e < NE; e++) {
            if (e == i0) continue;
            if (i1 < 0 || p[e] > p[i1]) i1 = e;
        }
        float v0 = p[i0], v1 = p[i1];
        float inv2 = 1.f / (v0 + v1);
        int s0 = atomicAdd(&g_count[i0], 1);
        g_tok[i0 * TMAX + s0] = t;  g_wt[i0 * TMAX + s0] = v0 * inv2;
        int s1 = atomicAdd(&g_count[i1], 1);
        g_tok[i1 * TMAX + s1] = t;  g_wt[i1 * TMAX + s1] = v1 * inv2;
    }
}

__global__ void loss_kernel(float* __restrict__ out_loss, int T) {
    if (threadIdx.x == 0) {
        const double ideal = 1.0 / NE;
        double l = 0.0;
        #pragma unroll
        for (int e = 0; e < NE; e++) {
            double mp = g_probsum[e] / (double)T + 1e-9;
            l += ideal * (log(ideal) - log(mp));
        }
        *out_loss = (float)l;
    }
}

// ---------------------------------------------------------------------------
// Fused GU: CTA computes 128x64 tile of BOTH G and U, epilogue does
// silu(g)*u in-register and writes fp16 half2-packed Hp directly.
// A fp16, B 2-term hi/lo split. Warp grid 4(m) x 2(n), warptile 32x32 per matrix.
__global__ __launch_bounds__(256, 2)
void gu_kernel(const float* __restrict__ x,
               const float* __restrict__ Wg, const float* __restrict__ bg,
               const float* __restrict__ Wu, const float* __restrict__ bu) {
    int e = blockIdx.z;
    int n = g_count[e];
    int rowbase = blockIdx.y * 128;
    if (rowbase >= n) return;
    int colbase = blockIdx.x * 64;

    const float* WG = Wg + (size_t)e * D_MODEL * D_FF;
    const float* WU = Wu + (size_t)e * D_MODEL * D_FF;

    extern __shared__ char sm[];
    __shared__ int toks[128];
    uint32_t sbase = smem_u32(sm);

    int tid = threadIdx.x, lane = tid & 31, wid = tid >> 5;
    int wm = wid >> 1, wn = wid & 1;

    if (tid < 128) {
        int r = rowbase + tid;
        toks[tid] = g_tok[e * TMAX + (r < n ? r : n - 1)];
    }
    __syncthreads();

    float4 aReg[4], bgReg[2], buReg[2];
    auto ldg = [&](int k0) {
        #pragma unroll
        for (int it = 0; it < 4; it++) {
            int idx = tid + it * 256;
            int arow = idx >> 3, aseg = idx & 7;
            aReg[it] = *(const float4*)(x + (size_t)toks[arow] * D_MODEL + k0 + aseg * 4);
        }
        #pragma unroll
        for (int it = 0; it < 2; it++) {
            int idx = tid + it * 256;
            int brow = idx >> 4, bcol = (idx & 15) * 4;
            bgReg[it] = *(const float4*)(WG + (size_t)(k0 + brow) * D_FF + colbase + bcol);
            buReg[it] = *(const float4*)(WU + (size_t)(k0 + brow) * D_FF + colbase + bcol);
        }
    };
    auto sts = [&](int buf) {
        char* st = sm + buf * STAGE_GU;
        #pragma unroll
        for (int it = 0; it < 4; it++) {
            int idx = tid + it * 256;
            int arow = idx >> 3, aseg = idx & 7;
            uint32_t a01 = cvt2(aReg[it].x, aReg[it].y);
            uint32_t a23 = cvt2(aReg[it].z, aReg[it].w);
            *(uint2*)(st + arow * STRA + aseg * 8) = make_uint2(a01, a23);
        }
        #pragma unroll
        for (int it = 0; it < 2; it++) {
            int idx = tid + it * 256;
            int brow = idx >> 4, bcol = (idx & 15) * 4;
            uint32_t h0, h1, l0, l1;
            split2(bgReg[it].x, bgReg[it].y, h0, l0);
            split2(bgReg[it].z, bgReg[it].w, h1, l1);
            *(uint2*)(st + A_SZ + brow * STRB2 + bcol * 2)           = make_uint2(h0, h1);
            *(uint2*)(st + A_SZ + B2_SZ + brow * STRB2 + bcol * 2)   = make_uint2(l0, l1);
            split2(buReg[it].x, buReg[it].y, h0, l0);
            split2(buReg[it].z, buReg[it].w, h1, l1);
            *(uint2*)(st + A_SZ + 2 * B2_SZ + brow * STRB2 + bcol * 2) = make_uint2(h0, h1);
            *(uint2*)(st + A_SZ + 3 * B2_SZ + brow * STRB2 + bcol * 2) = make_uint2(l0, l1);
        }
    };

    float accG[2][4][4] = {}, accU[2][4][4] = {};
    int ar = lane & 15, ac = lane >> 4;          // A ldsm addr parts
    int kr = lane & 7,  sel = lane >> 3;         // B ldsm addr parts

    auto compute = [&](int buf) {
        uint32_t Ah  = sbase + buf * STAGE_GU;
        uint32_t BGh = Ah + A_SZ;
        uint32_t BGl = BGh + B2_SZ;
        uint32_t BUh = BGl + B2_SZ;
        uint32_t BUl = BUh + B2_SZ;
        #pragma unroll
        for (int ks = 0; ks < 2; ks++) {
            uint32_t ah[2][4], bgh[8], bgl[8], buh[8], bul[8];
            #pragma unroll
            for (int mt = 0; mt < 2; mt++) {
                uint32_t off = (uint32_t)((wm * 32 + mt * 16 + ar) * STRA + (ks * 16 + ac * 8) * 2);
                ldsm_x4(ah[mt], Ah + off);
            }
            #pragma unroll
            for (int nt2 = 0; nt2 < 2; nt2++) {
                int rowk = ks * 16 + (sel & 1) * 8 + kr;
                int coln = wn * 32 + nt2 * 16 + (sel >> 1) * 8;
                uint32_t off = (uint32_t)(rowk * STRB2 + coln * 2);
                ldsm_x4t(&bgh[nt2 * 4], BGh + off);
                ldsm_x4t(&bgl[nt2 * 4], BGl + off);
                ldsm_x4t(&buh[nt2 * 4], BUh + off);
                ldsm_x4t(&bul[nt2 * 4], BUl + off);
            }
            #pragma unroll
            for (int mt = 0; mt < 2; mt++)
                #pragma unroll
                for (int nt = 0; nt < 4; nt++) {
                    int bo = (nt >> 1) * 4 + (nt & 1) * 2;
                    mma16816(accG[mt][nt], ah[mt], &bgh[bo]);
                    mma16816(accG[mt][nt], ah[mt], &bgl[bo]);
                    mma16816(accU[mt][nt], ah[mt], &buh[bo]);
                    mma16816(accU[mt][nt], ah[mt], &bul[bo]);
                }
        }
    };

    const int NIT = D_MODEL / BK;   // 32
    ldg(0); sts(0);
    for (int i = 0; i < NIT; i++) {
        __syncthreads();
        if (i + 1 < NIT) ldg((i + 1) * BK);
        compute(i & 1);
        if (i + 1 < NIT) sts((i + 1) & 1);
    }

    // epilogue: h = silu(g+bg)*(u+bu), write fp16 half2-packed Hp
    const float* bgp = bg + e * D_FF + colbase;
    const float* bup = bu + e * D_FF + colbase;
    #pragma unroll
    for (int mt = 0; mt < 2; mt++) {
        int r0 = rowbase + wm * 32 + mt * 16 + (lane >> 2);
        #pragma unroll
        for (int nt = 0; nt < 4; nt++) {
            int c = wn * 32 + nt * 8 + (lane & 3) * 2;
            float bg0 = bgp[c], bg1 = bgp[c + 1];
            float bu0 = bup[c], bu1 = bup[c + 1];
            #pragma unroll
            for (int half = 0; half < 2; half++) {
                int r = r0 + half * 8;
                if (r >= n) continue;
                float g0 = accG[mt][nt][half * 2]     + bg0;
                float g1 = accG[mt][nt][half * 2 + 1] + bg1;
                float u0 = accU[mt][nt][half * 2]     + bu0;
                float u1 = accU[mt][nt][half * 2 + 1] + bu1;
                float h0 = g0 / (1.f + __expf(-g0)) * u0;
                float h1 = g1 / (1.f + __expf(-g1)) * u1;
                g_Hp[((size_t)e * TMAX + r) * (D_FF / 2) + (colbase + c) / 2] = cvt2(h0, h1);
            }
        }
    }
}

// ---------------------------------------------------------------------------
// Down: out[t] += w * ( H @ Wd + bd ), A = fp16 H (copy), B split, split-K=2.
__global__ __launch_bounds__(256, 2)
void dn_kernel(const float* __restrict__ Wd, const float* __restrict__ bd,
               float* __restrict__ out) {
    int e  = blockIdx.z >> 1;
    int kb = blockIdx.z & 1;
    int n = g_count[e];
    int rowbase = blockIdx.y * 128;
    if (rowbase >= n) return;
    int colbase = blockIdx.x * 128;
    int kbase = kb * (D_FF / 2);

    const float*    W  = Wd + (size_t)e * D_FF * D_MODEL;
    const uint32_t* Hp = g_Hp + (size_t)e * TMAX * (D_FF / 2);

    extern __shared__ char sm[];
    uint32_t sbase = smem_u32(sm);

    int tid = threadIdx.x, lane = tid & 31, wid = tid >> 5;
    int wm = wid >> 2, wn = wid & 3;

    uint2  aReg[4];
    float4 bReg[4];
    auto ldg = [&](int k0) {
        #pragma unroll
        for (int it = 0; it < 4; it++) {
            int idx = tid + it * 256;
            int arow = idx >> 3, aseg = idx & 7;
            int r = rowbase + arow; if (r >= n) r = n - 1;
            aReg[it] = *(const uint2*)(Hp + (size_t)r * (D_FF / 2) + ((kbase + k0) >> 1) + aseg * 2);
            int brow = idx >> 5, bseg = idx & 31;
            bReg[it] = *(const float4*)(W + (size_t)(kbase + k0 + brow) * D_MODEL + colbase + bseg * 4);
        }
    };
    auto sts = [&](int buf) {
        char* st = sm + buf * STAGE_DN;
        #pragma unroll
        for (int it = 0; it < 4; it++) {
            int idx = tid + it * 256;
            int arow = idx >> 3, aseg = idx & 7;
            *(uint2*)(st + arow * STRA + aseg * 8) = aReg[it];
            int brow = idx >> 5, bseg = idx & 31;
            uint32_t bh0, bh1, bl0, bl1;
            split2(bReg[it].x, bReg[it].y, bh0, bl0);
            split2(bReg[it].z, bReg[it].w, bh1, bl1);
            *(uint2*)(st + A_SZ + brow * STRB + bseg * 8)        = make_uint2(bh0, bh1);
            *(uint2*)(st + A_SZ + B_SZ + brow * STRB + bseg * 8) = make_uint2(bl0, bl1);
        }
    };

    float acc[4][4][4] = {};
    int ar = lane & 15, ac = lane >> 4;
    int kr = lane & 7,  sel = lane >> 3;

    auto compute = [&](int buf) {
        uint32_t Ah = sbase + buf * STAGE_DN;
        uint32_t Bh = Ah + A_SZ;
        uint32_t Bl = Bh + B_SZ;
        #pragma unroll
        for (int ks = 0; ks < 2; ks++) {
            uint32_t ah[4][4], bh[8], bl[8];
            #pragma unroll
            for (int mt = 0; mt < 4; mt++) {
                uint32_t off = (uint32_t)((wm * 64 + mt * 16 + ar) * STRA + (ks * 16 + ac * 8) * 2);
                ldsm_x4(ah[mt], Ah + off);
            }
            #pragma unroll
            for (int nt2 = 0; nt2 < 2; nt2++) {
                int rowk = ks * 16 + (sel & 1) * 8 + kr;
                int coln = wn * 32 + nt2 * 16 + (sel >> 1) * 8;
                uint32_t off = (uint32_t)(rowk * STRB + coln * 2);
                ldsm_x4t(&bh[nt2 * 4], Bh + off);
                ldsm_x4t(&bl[nt2 * 4], Bl + off);
            }
            #pragma unroll
            for (int mt = 0; mt < 4; mt++)
                #pragma unroll
                for (int nt = 0; nt < 4; nt++) {
                    const uint32_t* bhp = &bh[(nt >> 1) * 4 + (nt & 1) * 2];
                    const uint32_t* blp = &bl[(nt >> 1) * 4 + (nt & 1) * 2];
                    mma16816(acc[mt][nt], ah[mt], bhp);
                    mma16816(acc[mt][nt], ah[mt], blp);
                }
        }
    };

    const int NIT = (D_FF / 2) / BK;   // 32
    ldg(0); sts(0);
    for (int i = 0; i < NIT; i++) {
        __syncthreads();
        if (i + 1 < NIT) ldg((i + 1) * BK);
        compute(i & 1);
        if (i + 1 < NIT) sts((i + 1) & 1);
    }

    // epilogue: + bd (kb==0 only), * combine weight, atomic scatter into out
    #pragma unroll
    for (int mt = 0; mt < 4; mt++) {
        int r0 = rowbase + wm * 64 + mt * 16 + (lane >> 2);
        #pragma unroll
        for (int nt = 0; nt < 4; nt++) {
            int c = colbase + wn * 32 + nt * 8 + (lane & 3) * 2;
            float b0 = 0.f, b1 = 0.f;
            if (kb == 0) { b0 = bd[e * D_MODEL + c]; b1 = bd[e * D_MODEL + c + 1]; }
            if (r0 < n) {
                int t = g_tok[e * TMAX + r0];
                float w = g_wt[e * TMAX + r0];
                atomicAdd(&out[(size_t)t * D_MODEL + c],     w * (acc[mt][nt][0] + b0));
                atomicAdd(&out[(size_t)t * D_MODEL + c + 1], w * (acc[mt][nt][1] + b1));
            }
            if (r0 + 8 < n) {
                int t = g_tok[e * TMAX + r0 + 8];
                float w = g_wt[e * TMAX + r0 + 8];
                atomicAdd(&out[(size_t)t * D_MODEL + c],     w * (acc[mt][nt][2] + b0));
                atomicAdd(&out[(size_t)t * D_MODEL + c + 1], w * (acc[mt][nt][3] + b1));
            }
        }
    }
}

// ---------------------------------------------------------------------------
extern "C" void kernel_launch(void* const* d_in, const int* in_sizes, int n_in,
                              void* d_out, int out_size) {
    const float* x  = (const float*)d_in[0];
    const float* gw = (const float*)d_in[1];
    const float* gb = (const float*)d_in[2];
    const float* Wg = (const float*)d_in[3];
    const float* bg = (const float*)d_in[4];
    const float* Wu = (const float*)d_in[5];
    const float* bu = (const float*)d_in[6];
    const float* Wd = (const float*)d_in[7];
    const float* bd = (const float*)d_in[8];
    float* out = (float*)d_out;

    int T = in_sizes[0] / D_MODEL;   // 2048

    cudaFuncSetAttribute(gu_kernel, cudaFuncAttributeMaxDynamicSharedMemorySize, GU_DYN);
    cudaFuncSetAttribute(dn_kernel, cudaFuncAttributeMaxDynamicSharedMemorySize, DN_DYN);

    cudaMemsetAsync(out, 0, (size_t)T * D_MODEL * sizeof(float));
    zero_kernel<<<1, 32>>>();
    router_kernel<<<T, 256>>>(x, gw, gb);
    if (out_size > T * D_MODEL) {
        loss_kernel<<<1, 32>>>(out + (size_t)T * D_MODEL, T);
    }
    dim3 g1(D_FF / 64, TMAX / 128, NE);        // 32 x 16 x 8
    gu_kernel<<<g1, 256, GU_DYN>>>(x, Wg, bg, Wu, bu);
    dim3 g2(D_MODEL / 128, TMAX / 128, NE * 2); // 8 x 16 x 16 (split-K=2)
    dn_kernel<<<g2, 256, DN_DYN>>>(Wd, bd, out);
}

// round 10
// speedup vs baseline: 5.9734x; 1.3683x over previous
#include <cuda_runtime.h>
#include <cuda_fp16.h>
#include <math.h>
#include <stdint.h>

#define D_MODEL 1024
#define D_FF    2048
#define NE      8
#define TMAX    2048

#define BK 32
#define STRA 80                       // A smem row stride bytes (128 rows)
#define STRB2 144                     // fused-GU B row stride (64 cols fp16)
#define B2_SZ (32 * STRB2)            // 4608
#define A_SZ (128 * STRA)             // 10240
#define STAGE_GU (A_SZ + 2 * B2_SZ)   // 19456 (A | Bg | Bu)
#define GU_DYN (2 * STAGE_GU)         // 38912
#define STRB 272                      // dn B row stride (128 cols fp16)
#define B_SZ (32 * STRB)              // 8704
#define STAGE_DN (A_SZ + B_SZ)        // 18944 (A | B)
#define DN_DYN (2 * STAGE_DN)         // 37888

// -------- device scratch (static; no cudaMalloc allowed) --------
__device__ int      g_count[NE];
__device__ double   g_probsum[NE];
__device__ int      g_tok[NE * TMAX];
__device__ float    g_wt[NE * TMAX];
__device__ uint32_t g_Hp[(size_t)NE * TMAX * D_FF / 2];  // fp16 h, half2-packed

// ---------------- helpers ----------------
__device__ __forceinline__ uint32_t smem_u32(const void* p) {
    uint32_t a;
    asm("{ .reg .u64 t; cvta.to.shared.u64 t, %1; cvt.u32.u64 %0, t; }" : "=r"(a) : "l"(p));
    return a;
}
__device__ __forceinline__ uint32_t cvt2(float f0, float f1) {
    __half2 h = __floats2half2_rn(f0, f1);
    return *reinterpret_cast<uint32_t*>(&h);
}
__device__ __forceinline__ void ldsm_x4(uint32_t* r, uint32_t addr) {
    asm volatile("ldmatrix.sync.aligned.m8n8.x4.shared.b16 {%0,%1,%2,%3}, [%4];"
                 : "=r"(r[0]), "=r"(r[1]), "=r"(r[2]), "=r"(r[3]) : "r"(addr));
}
__device__ __forceinline__ void ldsm_x4t(uint32_t* r, uint32_t addr) {
    asm volatile("ldmatrix.sync.aligned.m8n8.x4.trans.shared.b16 {%0,%1,%2,%3}, [%4];"
                 : "=r"(r[0]), "=r"(r[1]), "=r"(r[2]), "=r"(r[3]) : "r"(addr));
}
__device__ __forceinline__ void mma16816(float* c, const uint32_t* a, const uint32_t* b) {
    asm volatile("mma.sync.aligned.m16n8k16.row.col.f32.f16.f16.f32 "
                 "{%0,%1,%2,%3}, {%4,%5,%6,%7}, {%8,%9}, {%0,%1,%2,%3};"
                 : "+f"(c[0]), "+f"(c[1]), "+f"(c[2]), "+f"(c[3])
                 : "r"(a[0]), "r"(a[1]), "r"(a[2]), "r"(a[3]), "r"(b[0]), "r"(b[1]));
}

// ---------------------------------------------------------------------------
__global__ void zero_kernel() {
    int i = threadIdx.x;
    if (i < NE) { g_count[i] = 0; g_probsum[i] = 0.0; }
}

__global__ void router_kernel(const float* __restrict__ x,
                              const float* __restrict__ gw,
                              const float* __restrict__ gb) {
    int t    = blockIdx.x;
    int warp = threadIdx.x >> 5;
    int lane = threadIdx.x & 31;
    __shared__ float logits[NE];

    const float* xr = x + (size_t)t * D_MODEL;
    const float* w  = gw + warp * D_MODEL;
    float s = 0.f;
    for (int i = lane; i < D_MODEL; i += 32) s += xr[i] * w[i];
    #pragma unroll
    for (int o = 16; o > 0; o >>= 1) s += __shfl_down_sync(0xffffffff, s, o);
    if (lane == 0) logits[warp] = s + gb[warp];
    __syncthreads();

    if (threadIdx.x == 0) {
        float p[NE];
        float mx = -1e30f;
        #pragma unroll
        for (int e = 0; e < NE; e++) mx = fmaxf(mx, logits[e]);
        float sum = 0.f;
        #pragma unroll
        for (int e = 0; e < NE; e++) { p[e] = expf(logits[e] - mx); sum += p[e]; }
        float inv = 1.f / sum;
        #pragma unroll
        for (int e = 0; e < NE; e++) {
            p[e] *= inv;
            atomicAdd(&g_probsum[e], (double)p[e]);
        }
        int i0 = 0;
        #pragma unroll
        for (int e = 1; e < NE; e++) if (p[e] > p[i0]) i0 = e;
        int i1 = -1;
        #pragma unroll
        for (int e = 0; e < NE; e++) {
            if (e == i0) continue;
            if (i1 < 0 || p[e] > p[i1]) i1 = e;
        }
        float v0 = p[i0], v1 = p[i1];
        float inv2 = 1.f / (v0 + v1);
        int s0 = atomicAdd(&g_count[i0], 1);
        g_tok[i0 * TMAX + s0] = t;  g_wt[i0 * TMAX + s0] = v0 * inv2;
        int s1 = atomicAdd(&g_count[i1], 1);
        g_tok[i1 * TMAX + s1] = t;  g_wt[i1 * TMAX + s1] = v1 * inv2;
    }
}

__global__ void loss_kernel(float* __restrict__ out_loss, int T) {
    if (threadIdx.x == 0) {
        const double ideal = 1.0 / NE;
        double l = 0.0;
        #pragma unroll
        for (int e = 0; e < NE; e++) {
            double mp = g_probsum[e] / (double)T + 1e-9;
            l += ideal * (log(ideal) - log(mp));
        }
        *out_loss = (float)l;
    }
}

// ---------------------------------------------------------------------------
// Fused GU: CTA computes 128x64 tile of BOTH G and U (all operands fp16),
// epilogue does silu(g)*u in-register, writes fp16 half2-packed Hp.
// Warp grid 4(m) x 2(n), warptile 32x32 per matrix.
__global__ __launch_bounds__(256, 2)
void gu_kernel(const float* __restrict__ x,
               const float* __restrict__ Wg, const float* __restrict__ bg,
               const float* __restrict__ Wu, const float* __restrict__ bu) {
    int e = blockIdx.z;
    int n = g_count[e];
    int rowbase = blockIdx.y * 128;
    if (rowbase >= n) return;
    int colbase = blockIdx.x * 64;

    const float* WG = Wg + (size_t)e * D_MODEL * D_FF;
    const float* WU = Wu + (size_t)e * D_MODEL * D_FF;

    extern __shared__ char sm[];
    __shared__ int toks[128];
    uint32_t sbase = smem_u32(sm);

    int tid = threadIdx.x, lane = tid & 31, wid = tid >> 5;
    int wm = wid >> 1, wn = wid & 1;

    if (tid < 128) {
        int r = rowbase + tid;
        toks[tid] = g_tok[e * TMAX + (r < n ? r : n - 1)];
    }
    __syncthreads();

    float4 aReg[4], bgReg[2], buReg[2];
    auto ldg = [&](int k0) {
        #pragma unroll
        for (int it = 0; it < 4; it++) {
            int idx = tid + it * 256;
            int arow = idx >> 3, aseg = idx & 7;
            aReg[it] = *(const float4*)(x + (size_t)toks[arow] * D_MODEL + k0 + aseg * 4);
        }
        #pragma unroll
        for (int it = 0; it < 2; it++) {
            int idx = tid + it * 256;
            int brow = idx >> 4, bcol = (idx & 15) * 4;
            bgReg[it] = *(const float4*)(WG + (size_t)(k0 + brow) * D_FF + colbase + bcol);
            buReg[it] = *(const float4*)(WU + (size_t)(k0 + brow) * D_FF + colbase + bcol);
        }
    };
    auto sts = [&](int buf) {
        char* st = sm + buf * STAGE_GU;
        #pragma unroll
        for (int it = 0; it < 4; it++) {
            int idx = tid + it * 256;
            int arow = idx >> 3, aseg = idx & 7;
            uint32_t a01 = cvt2(aReg[it].x, aReg[it].y);
            uint32_t a23 = cvt2(aReg[it].z, aReg[it].w);
            *(uint2*)(st + arow * STRA + aseg * 8) = make_uint2(a01, a23);
        }
        #pragma unroll
        for (int it = 0; it < 2; it++) {
            int idx = tid + it * 256;
            int brow = idx >> 4, bcol = (idx & 15) * 4;
            uint32_t g01 = cvt2(bgReg[it].x, bgReg[it].y);
            uint32_t g23 = cvt2(bgReg[it].z, bgReg[it].w);
            *(uint2*)(st + A_SZ + brow * STRB2 + bcol * 2) = make_uint2(g01, g23);
            uint32_t u01 = cvt2(buReg[it].x, buReg[it].y);
            uint32_t u23 = cvt2(buReg[it].z, buReg[it].w);
            *(uint2*)(st + A_SZ + B2_SZ + brow * STRB2 + bcol * 2) = make_uint2(u01, u23);
        }
    };

    float accG[2][4][4] = {}, accU[2][4][4] = {};
    int ar = lane & 15, ac = lane >> 4;          // A ldsm addr parts
    int kr = lane & 7,  sel = lane >> 3;         // B ldsm addr parts

    auto compute = [&](int buf) {
        uint32_t Ah  = sbase + buf * STAGE_GU;
        uint32_t BGh = Ah + A_SZ;
        uint32_t BUh = BGh + B2_SZ;
        #pragma unroll
        for (int ks = 0; ks < 2; ks++) {
            uint32_t ah[2][4], bgh[8], buh[8];
            #pragma unroll
            for (int mt = 0; mt < 2; mt++) {
                uint32_t off = (uint32_t)((wm * 32 + mt * 16 + ar) * STRA + (ks * 16 + ac * 8) * 2);
                ldsm_x4(ah[mt], Ah + off);
            }
            #pragma unroll
            for (int nt2 = 0; nt2 < 2; nt2++) {
                int rowk = ks * 16 + (sel & 1) * 8 + kr;
                int coln = wn * 32 + nt2 * 16 + (sel >> 1) * 8;
                uint32_t off = (uint32_t)(rowk * STRB2 + coln * 2);
                ldsm_x4t(&bgh[nt2 * 4], BGh + off);
                ldsm_x4t(&buh[nt2 * 4], BUh + off);
            }
            #pragma unroll
            for (int mt = 0; mt < 2; mt++)
                #pragma unroll
                for (int nt = 0; nt < 4; nt++) {
                    int bo = (nt >> 1) * 4 + (nt & 1) * 2;
                    mma16816(accG[mt][nt], ah[mt], &bgh[bo]);
                    mma16816(accU[mt][nt], ah[mt], &buh[bo]);
                }
        }
    };

    const int NIT = D_MODEL / BK;   // 32
    ldg(0); sts(0);
    for (int i = 0; i < NIT; i++) {
        __syncthreads();
        if (i + 1 < NIT) ldg((i + 1) * BK);
        compute(i & 1);
        if (i + 1 < NIT) sts((i + 1) & 1);
    }

    // epilogue: h = silu(g+bg)*(u+bu), write fp16 half2-packed Hp
    const float* bgp = bg + e * D_FF + colbase;
    const float* bup = bu + e * D_FF + colbase;
    #pragma unroll
    for (int mt = 0; mt < 2; mt++) {
        int r0 = rowbase + wm * 32 + mt * 16 + (lane >> 2);
        #pragma unroll
        for (int nt = 0; nt < 4; nt++) {
            int c = wn * 32 + nt * 8 + (lane & 3) * 2;
            float bg0 = bgp[c], bg1 = bgp[c + 1];
            float bu0 = bup[c], bu1 = bup[c + 1];
            #pragma unroll
            for (int half = 0; half < 2; half++) {
                int r = r0 + half * 8;
                if (r >= n) continue;
                float g0 = accG[mt][nt][half * 2]     + bg0;
                float g1 = accG[mt][nt][half * 2 + 1] + bg1;
                float u0 = accU[mt][nt][half * 2]     + bu0;
                float u1 = accU[mt][nt][half * 2 + 1] + bu1;
                float h0 = g0 / (1.f + __expf(-g0)) * u0;
                float h1 = g1 / (1.f + __expf(-g1)) * u1;
                g_Hp[((size_t)e * TMAX + r) * (D_FF / 2) + (colbase + c) / 2] = cvt2(h0, h1);
            }
        }
    }
}

// ---------------------------------------------------------------------------
// Down: out[t] += w * ( H @ Wd + bd ), all fp16 operands, split-K=2.
__global__ __launch_bounds__(256, 2)
void dn_kernel(const float* __restrict__ Wd, const float* __restrict__ bd,
               float* __restrict__ out) {
    int e  = blockIdx.z >> 1;
    int kb = blockIdx.z & 1;
    int n = g_count[e];
    int rowbase = blockIdx.y * 128;
    if (rowbase >= n) return;
    int colbase = blockIdx.x * 128;
    int kbase = kb * (D_FF / 2);

    const float*    W  = Wd + (size_t)e * D_FF * D_MODEL;
    const uint32_t* Hp = g_Hp + (size_t)e * TMAX * (D_FF / 2);

    extern __shared__ char sm[];
    uint32_t sbase = smem_u32(sm);

    int tid = threadIdx.x, lane = tid & 31, wid = tid >> 5;
    int wm = wid >> 2, wn = wid & 3;

    uint2  aReg[4];
    float4 bReg[4];
    auto ldg = [&](int k0) {
        #pragma unroll
        for (int it = 0; it < 4; it++) {
            int idx = tid + it * 256;
            int arow = idx >> 3, aseg = idx & 7;
            int r = rowbase + arow; if (r >= n) r = n - 1;
            aReg[it] = *(const uint2*)(Hp + (size_t)r * (D_FF / 2) + ((kbase + k0) >> 1) + aseg * 2);
            int brow = idx >> 5, bseg = idx & 31;
            bReg[it] = *(const float4*)(W + (size_t)(kbase + k0 + brow) * D_MODEL + colbase + bseg * 4);
        }
    };
    auto sts = [&](int buf) {
        char* st = sm + buf * STAGE_DN;
        #pragma unroll
        for (int it = 0; it < 4; it++) {
            int idx = tid + it * 256;
            int arow = idx >> 3, aseg = idx & 7;
            *(uint2*)(st + arow * STRA + aseg * 8) = aReg[it];
            int brow = idx >> 5, bseg = idx & 31;
            uint32_t b01 = cvt2(bReg[it].x, bReg[it].y);
            uint32_t b23 = cvt2(bReg[it].z, bReg[it].w);
            *(uint2*)(st + A_SZ + brow * STRB + bseg * 8) = make_uint2(b01, b23);
        }
    };

    float acc[4][4][4] = {};
    int ar = lane & 15, ac = lane >> 4;
    int kr = lane & 7,  sel = lane >> 3;

    auto compute = [&](int buf) {
        uint32_t Ah = sbase + buf * STAGE_DN;
        uint32_t Bh = Ah + A_SZ;
        #pragma unroll
        for (int ks = 0; ks < 2; ks++) {
            uint32_t ah[4][4], bh[8];
            #pragma unroll
            for (int mt = 0; mt < 4; mt++) {
                uint32_t off = (uint32_t)((wm * 64 + mt * 16 + ar) * STRA + (ks * 16 + ac * 8) * 2);
                ldsm_x4(ah[mt], Ah + off);
            }
            #pragma unroll
            for (int nt2 = 0; nt2 < 2; nt2++) {
                int rowk = ks * 16 + (sel & 1) * 8 + kr;
                int coln = wn * 32 + nt2 * 16 + (sel >> 1) * 8;
                uint32_t off = (uint32_t)(rowk * STRB + coln * 2);
                ldsm_x4t(&bh[nt2 * 4], Bh + off);
            }
            #pragma unroll
            for (int mt = 0; mt < 4; mt++)
                #pragma unroll
                for (int nt = 0; nt < 4; nt++) {
                    const uint32_t* bhp = &bh[(nt >> 1) * 4 + (nt & 1) * 2];
                    mma16816(acc[mt][nt], ah[mt], bhp);
                }
        }
    };

    const int NIT = (D_FF / 2) / BK;   // 32
    ldg(0); sts(0);
    for (int i = 0; i < NIT; i++) {
        __syncthreads();
        if (i + 1 < NIT) ldg((i + 1) * BK);
        compute(i & 1);
        if (i + 1 < NIT) sts((i + 1) & 1);
    }

    // epilogue: + bd (kb==0 only), * combine weight, atomic scatter into out
    #pragma unroll
    for (int mt = 0; mt < 4; mt++) {
        int r0 = rowbase + wm * 64 + mt * 16 + (lane >> 2);
        #pragma unroll
        for (int nt = 0; nt < 4; nt++) {
            int c = colbase + wn * 32 + nt * 8 + (lane & 3) * 2;
            float b0 = 0.f, b1 = 0.f;
            if (kb == 0) { b0 = bd[e * D_MODEL + c]; b1 = bd[e * D_MODEL + c + 1]; }
            if (r0 < n) {
                int t = g_tok[e * TMAX + r0];
                float w = g_wt[e * TMAX + r0];
                atomicAdd(&out[(size_t)t * D_MODEL + c],     w * (acc[mt][nt][0] + b0));
                atomicAdd(&out[(size_t)t * D_MODEL + c + 1], w * (acc[mt][nt][1] + b1));
            }
            if (r0 + 8 < n) {
                int t = g_tok[e * TMAX + r0 + 8];
                float w = g_wt[e * TMAX + r0 + 8];
                atomicAdd(&out[(size_t)t * D_MODEL + c],     w * (acc[mt][nt][2] + b0));
                atomicAdd(&out[(size_t)t * D_MODEL + c + 1], w * (acc[mt][nt][3] + b1));
            }
        }
    }
}

// ---------------------------------------------------------------------------
extern "C" void kernel_launch(void* const* d_in, const int* in_sizes, int n_in,
                              void* d_out, int out_size) {
    const float* x  = (const float*)d_in[0];
    const float* gw = (const float*)d_in[1];
    const float* gb = (const float*)d_in[2];
    const float* Wg = (const float*)d_in[3];
    const float* bg = (const float*)d_in[4];
    const float* Wu = (const float*)d_in[5];
    const float* bu = (const float*)d_in[6];
    const float* Wd = (const float*)d_in[7];
    const float* bd = (const float*)d_in[8];
    float* out = (float*)d_out;

    int T = in_sizes[0] / D_MODEL;   // 2048

    cudaFuncSetAttribute(gu_kernel, cudaFuncAttributeMaxDynamicSharedMemorySize, GU_DYN);
    cudaFuncSetAttribute(dn_kernel, cudaFuncAttributeMaxDynamicSharedMemorySize, DN_DYN);

    cudaMemsetAsync(out, 0, (size_t)T * D_MODEL * sizeof(float));
    zero_kernel<<<1, 32>>>();
    router_kernel<<<T, 256>>>(x, gw, gb);
    if (out_size > T * D_MODEL) {
        loss_kernel<<<1, 32>>>(out + (size_t)T * D_MODEL, T);
    }
    dim3 g1(D_FF / 64, TMAX / 128, NE);        // 32 x 16 x 8
    gu_kernel<<<g1, 256, GU_DYN>>>(x, Wg, bg, Wu, bu);
    dim3 g2(D_MODEL / 128, TMAX / 128, NE * 2); // 8 x 16 x 16 (split-K=2)
    dn_kernel<<<g2, 256, DN_DYN>>>(Wd, bd, out);
}